// round 2
// baseline (speedup 1.0000x reference)
#include <cuda_runtime.h>
#include <math.h>

// Problem constants (fixed shapes from reference)
#define NN 48
#define CC 512
#define PP 1600      // 40*40
#define KK 64
#define KC 32768     // K*C
#define NPT 25       // P / 64 tiles

// ---------------- scratch (static device memory; no runtime allocs) --------
__device__ float g_invn[NN * PP];          // 1/max(||x||,eps) per (n,p)
__device__ float g_hmp [NN * PP];          // heatmap per (n,p)
__device__ float g_w   [(size_t)NN * PP * KK];   // w  = softmax*hmp,    layout [n][p][k]
__device__ float g_w2  [(size_t)NN * PP * KK];   // w2 = w*invn,         layout [n][p][k]
__device__ float g_wsp [NN * NPT * KK];    // partial wsum per p-tile  [n][pt][k]
__device__ float g_convT[CC * KK];         // conv_w transposed [c][k]
__device__ float g_gpart[NN * KK];         // per-(n,k) contribution to global norm^2

// ---------------- kernel P: transpose conv_w (one-time tiny) ---------------
__global__ void k_transpose(const float* __restrict__ conv_w) {
    int i = blockIdx.x * 256 + threadIdx.x;   // i = c*64 + k
    if (i < CC * KK) {
        int c = i >> 6, k = i & 63;
        g_convT[i] = conv_w[k * CC + c];
    }
}

// ---------------- kernel A: per-pixel inv_norm + heatmap -------------------
__global__ __launch_bounds__(256) void k_prep(const float* __restrict__ x,
                                              const float* __restrict__ aw,
                                              const float* __restrict__ ab) {
    __shared__ float saw[CC];
    int tid = threadIdx.x;
    for (int i = tid; i < CC; i += 256) saw[i] = aw[i];
    __syncthreads();

    int idx = blockIdx.x * 256 + tid;          // 0 .. N*P-1
    int n = idx / PP, p = idx - n * PP;
    const float* xp = x + (size_t)n * CC * PP + p;
    float ss = 0.f, hs = 0.f;
#pragma unroll 8
    for (int c = 0; c < CC; c++) {
        float v = xp[(size_t)c * PP];
        ss += v * v;
        hs += fmaxf(v, 0.f) * saw[c];
    }
    g_invn[idx] = 1.f / fmaxf(sqrtf(ss), 1e-12f);
    g_hmp[idx]  = fmaxf(hs + ab[0], 0.f);
}

// ---------------- kernel B: GEMM1 (logits) + fused softmax -----------------
// block = (p-tile of 64, n). Computes logits[k=0..63][p-tile], softmax over k,
// writes w, w2 in [n][p][k] layout + partial wsum for the tile.
struct SmemG { float cws[32][68]; float xs[32][68]; };  // [c-chunk][k], [c-chunk][p]
struct SmemS { float S[64][65]; float ps[8][64]; };     // [p][k] logits, warp partials
union SmemU { SmemG g; SmemS s; };

__global__ __launch_bounds__(256) void k_assign(const float* __restrict__ x) {
    __shared__ __align__(16) SmemU u;
    int pt = blockIdx.x, n = blockIdx.y;
    int p0 = pt * 64;
    int tid = threadIdx.x;
    int tx = tid & 15, ty = tid >> 4;          // tx -> p group, ty -> k group

    float acc[4][4] = {};
    for (int c0 = 0; c0 < CC; c0 += 32) {
        for (int i = tid; i < 2048; i += 256) {   // conv^T chunk: [cc][k]
            int cc = i >> 6, k = i & 63;
            u.g.cws[cc][k] = g_convT[(c0 + cc) * KK + k];
        }
        for (int i = tid; i < 2048; i += 256) {   // x chunk: [cc][p]
            int cc = i >> 6, p = i & 63;
            u.g.xs[cc][p] = x[((size_t)(n * CC + c0 + cc)) * PP + p0 + p];
        }
        __syncthreads();
#pragma unroll 8
        for (int cc = 0; cc < 32; cc++) {
            float4 av = *reinterpret_cast<const float4*>(&u.g.cws[cc][ty * 4]);
            float4 bv = *reinterpret_cast<const float4*>(&u.g.xs[cc][tx * 4]);
            float a[4] = {av.x, av.y, av.z, av.w};
            float b[4] = {bv.x, bv.y, bv.z, bv.w};
#pragma unroll
            for (int i = 0; i < 4; i++)
#pragma unroll
                for (int j = 0; j < 4; j++) acc[i][j] += a[i] * b[j];
        }
        __syncthreads();
    }

    // scale logits by inv_norm and stage as S[p][k]
#pragma unroll
    for (int j = 0; j < 4; j++) {
        float iv = g_invn[n * PP + p0 + tx * 4 + j];
#pragma unroll
        for (int i = 0; i < 4; i++) u.s.S[tx * 4 + j][ty * 4 + i] = acc[i][j] * iv;
    }
    __syncthreads();

    // softmax over k (64) per p-row; 8 warps x 8 rows each
    int lane = tid & 31, wrp = tid >> 5;
    float pa = 0.f, pb = 0.f;
    for (int r8 = 0; r8 < 8; r8++) {
        int r = wrp * 8 + r8;
        float v0 = u.s.S[r][lane];
        float v1 = u.s.S[r][lane + 32];
        float m = fmaxf(v0, v1);
#pragma unroll
        for (int o = 16; o > 0; o >>= 1) m = fmaxf(m, __shfl_xor_sync(0xffffffffu, m, o));
        float e0 = __expf(v0 - m), e1 = __expf(v1 - m);
        float s = e0 + e1;
#pragma unroll
        for (int o = 16; o > 0; o >>= 1) s += __shfl_xor_sync(0xffffffffu, s, o);
        float h  = g_hmp [n * PP + p0 + r];
        float iv = g_invn[n * PP + p0 + r];
        float sc = h / s;
        float w0 = e0 * sc, w1 = e1 * sc;
        size_t base = ((size_t)n * PP + p0 + r) * KK;
        g_w [base + lane]      = w0;
        g_w [base + lane + 32] = w1;
        g_w2[base + lane]      = w0 * iv;
        g_w2[base + lane + 32] = w1 * iv;
        pa += w0; pb += w1;
    }
    u.s.ps[wrp][lane]      = pa;
    u.s.ps[wrp][lane + 32] = pb;
    __syncthreads();
    if (tid < 64) {
        float s = 0.f;
#pragma unroll
        for (int w = 0; w < 8; w++) s += u.s.ps[w][tid];
        g_wsp[(n * NPT + pt) * KK + tid] = s;
    }
}

// ---------------- kernel C: GEMM2 (term1 -> d_out) -------------------------
// block = (c-tile of 64, n), output tile [k=64][c=64], reduce over all P.
__global__ __launch_bounds__(256) void k_vlad(const float* __restrict__ x,
                                              float* __restrict__ out) {
    __shared__ __align__(16) float ws [32][68];   // [pp][k]
    __shared__ __align__(16) float xsT[32][68];   // [pp][c]
    int ct = blockIdx.x, n = blockIdx.y;
    int c0 = ct * 64;
    int tid = threadIdx.x;
    int tx = tid & 15, ty = tid >> 4;             // tx -> c group, ty -> k group

    float acc[4][4] = {};
    for (int pc = 0; pc < PP; pc += 32) {
        for (int i = tid; i < 2048; i += 256) {   // w2 chunk: [pp][k]
            int pp = i >> 6, k = i & 63;
            ws[pp][k] = g_w2[((size_t)n * PP + pc + pp) * KK + k];
        }
        for (int i = tid; i < 2048; i += 256) {   // x chunk transposed: [pp][c]
            int c = i >> 5, pp = i & 31;
            xsT[pp][c] = x[((size_t)(n * CC + c0 + c)) * PP + pc + pp];
        }
        __syncthreads();
#pragma unroll 8
        for (int pp = 0; pp < 32; pp++) {
            float4 av = *reinterpret_cast<const float4*>(&ws [pp][ty * 4]);
            float4 bv = *reinterpret_cast<const float4*>(&xsT[pp][tx * 4]);
            float a[4] = {av.x, av.y, av.z, av.w};
            float b[4] = {bv.x, bv.y, bv.z, bv.w};
#pragma unroll
            for (int i = 0; i < 4; i++)
#pragma unroll
                for (int j = 0; j < 4; j++) acc[i][j] += a[i] * b[j];
        }
        __syncthreads();
    }
    // write term1 to out[n][k*512 + c], float4 per (i)
#pragma unroll
    for (int i = 0; i < 4; i++) {
        float4 v = make_float4(acc[i][0], acc[i][1], acc[i][2], acc[i][3]);
        size_t o = (size_t)n * KC + (size_t)(ty * 4 + i) * CC + c0 + tx * 4;
        *reinterpret_cast<float4*>(out + o) = v;
    }
}

// ---------------- kernel E: vlad residual + intra L2 normalize -------------
__global__ __launch_bounds__(256) void k_norm1(const float* __restrict__ cent,
                                               float* __restrict__ out) {
    __shared__ float red[256];
    int k = blockIdx.x, n = blockIdx.y, tid = threadIdx.x;
    float wsum = 0.f;
#pragma unroll
    for (int t = 0; t < NPT; t++) wsum += g_wsp[(n * NPT + t) * KK + k];

    size_t base = (size_t)n * KC + (size_t)k * CC;
    float v1 = out[base + tid]       - wsum * cent[k * CC + tid];
    float v2 = out[base + tid + 256] - wsum * cent[k * CC + tid + 256];
    red[tid] = v1 * v1 + v2 * v2;
    __syncthreads();
    for (int o = 128; o > 0; o >>= 1) {
        if (tid < o) red[tid] += red[tid + o];
        __syncthreads();
    }
    float tot = red[0];
    float inv = 1.f / fmaxf(sqrtf(tot), 1e-12f);
    out[base + tid]       = v1 * inv;
    out[base + tid + 256] = v2 * inv;
    if (tid == 0) g_gpart[n * KK + k] = tot * inv * inv;
}

// ---------------- kernel F: global L2 normalize ----------------------------
__global__ __launch_bounds__(256) void k_norm2(float* __restrict__ out) {
    __shared__ float s[KK];
    __shared__ float ginv;
    size_t i = (size_t)blockIdx.x * 256 + threadIdx.x;
    int n = (int)(i >> 15);                    // 32768 elements per n
    if (threadIdx.x < KK) s[threadIdx.x] = g_gpart[n * KK + threadIdx.x];
    __syncthreads();
    if (threadIdx.x == 0) {
        float t = 0.f;
#pragma unroll
        for (int j = 0; j < KK; j++) t += s[j];
        ginv = 1.f / fmaxf(sqrtf(t), 1e-12f);
    }
    __syncthreads();
    out[i] *= ginv;
}

// ---------------- launch ---------------------------------------------------
extern "C" void kernel_launch(void* const* d_in, const int* in_sizes, int n_in,
                              void* d_out, int out_size) {
    const float* x      = (const float*)d_in[0];
    const float* conv_w = (const float*)d_in[1];
    const float* attn_w = (const float*)d_in[2];
    const float* attn_b = (const float*)d_in[3];
    const float* cent   = (const float*)d_in[4];
    float* out = (float*)d_out;
    (void)in_sizes; (void)n_in; (void)out_size;

    k_transpose<<<(CC * KK + 255) / 256, 256>>>(conv_w);
    k_prep<<<NN * PP / 256, 256>>>(x, attn_w, attn_b);
    k_assign<<<dim3(NPT, NN), 256>>>(x);
    k_vlad<<<dim3(CC / 64, NN), 256>>>(x, out);
    k_norm1<<<dim3(KK, NN), 256>>>(cent, out);
    k_norm2<<<(NN * KC) / 256, 256>>>(out);
}

// round 3
// speedup vs baseline: 1.2253x; 1.2253x over previous
#include <cuda_runtime.h>
#include <math.h>

// Problem constants (fixed shapes from reference)
#define NN 48
#define CC 512
#define PP 1600      // 40*40
#define KK 64
#define KC 32768     // K*C
#define NPT 25       // P / 64 tiles (k_assign)

// k_vlad tiling
#define CT 128       // c tile
#define NSPLIT 10    // split-P factor
#define PSP 160      // P per split
#define CHK 16       // pp chunk

// ---------------- scratch (static device memory; no runtime allocs) --------
__device__ float g_invn[NN * PP];          // 1/max(||x||,eps) per (n,p)
__device__ float g_hmp [NN * PP];          // heatmap per (n,p)
__device__ float g_w2  [(size_t)NN * PP * KK];   // w2 = softmax*hmp*invn, layout [n][p][k]
__device__ float g_wsp [NN * NPT * KK];    // partial wsum per p-tile  [n][pt][k]
__device__ float g_convT[CC * KK];         // conv_w transposed [c][k]
__device__ float g_gpart[NN * KK];         // per-(n,k) contribution to global norm^2
__device__ float g_vp  [(size_t)NSPLIT * NN * KK * CC];  // GEMM2 partials [s][n][k][c]

// ---------------- kernel P: transpose conv_w (one-time tiny) ---------------
__global__ void k_transpose(const float* __restrict__ conv_w) {
    int i = blockIdx.x * 256 + threadIdx.x;   // i = c*64 + k
    if (i < CC * KK) {
        int c = i >> 6, k = i & 63;
        g_convT[i] = conv_w[k * CC + c];
    }
}

// ---------------- kernel A: per-pixel inv_norm + heatmap -------------------
__global__ __launch_bounds__(256) void k_prep(const float* __restrict__ x,
                                              const float* __restrict__ aw,
                                              const float* __restrict__ ab) {
    __shared__ float saw[CC];
    int tid = threadIdx.x;
    for (int i = tid; i < CC; i += 256) saw[i] = aw[i];
    __syncthreads();

    int idx = blockIdx.x * 256 + tid;          // 0 .. N*P-1
    int n = idx / PP, p = idx - n * PP;
    const float* xp = x + (size_t)n * CC * PP + p;
    float ss = 0.f, hs = 0.f;
#pragma unroll 8
    for (int c = 0; c < CC; c++) {
        float v = xp[(size_t)c * PP];
        ss += v * v;
        hs += fmaxf(v, 0.f) * saw[c];
    }
    g_invn[idx] = 1.f / fmaxf(sqrtf(ss), 1e-12f);
    g_hmp[idx]  = fmaxf(hs + ab[0], 0.f);
}

// ---------------- kernel B: GEMM1 (logits) + fused softmax -----------------
// block = (p-tile of 64, n). Computes logits[k=0..63][p-tile], softmax over k,
// writes w2 in [n][p][k] layout + partial wsum for the tile.
struct SmemG { float cws[32][68]; float xs[32][68]; };  // [c-chunk][k], [c-chunk][p]
struct SmemS { float S[64][65]; float ps[8][64]; };     // [p][k] logits, warp partials
union SmemU { SmemG g; SmemS s; };

__global__ __launch_bounds__(256) void k_assign(const float* __restrict__ x) {
    __shared__ __align__(16) SmemU u;
    int pt = blockIdx.x, n = blockIdx.y;
    int p0 = pt * 64;
    int tid = threadIdx.x;
    int tx = tid & 15, ty = tid >> 4;          // tx -> p group, ty -> k group

    float acc[4][4] = {};
    for (int c0 = 0; c0 < CC; c0 += 32) {
        for (int i = tid; i < 2048; i += 256) {   // conv^T chunk: [cc][k]
            int cc = i >> 6, k = i & 63;
            u.g.cws[cc][k] = g_convT[(c0 + cc) * KK + k];
        }
        for (int i = tid; i < 2048; i += 256) {   // x chunk: [cc][p]
            int cc = i >> 6, p = i & 63;
            u.g.xs[cc][p] = x[((size_t)(n * CC + c0 + cc)) * PP + p0 + p];
        }
        __syncthreads();
#pragma unroll 8
        for (int cc = 0; cc < 32; cc++) {
            float4 av = *reinterpret_cast<const float4*>(&u.g.cws[cc][ty * 4]);
            float4 bv = *reinterpret_cast<const float4*>(&u.g.xs[cc][tx * 4]);
            float a[4] = {av.x, av.y, av.z, av.w};
            float b[4] = {bv.x, bv.y, bv.z, bv.w};
#pragma unroll
            for (int i = 0; i < 4; i++)
#pragma unroll
                for (int j = 0; j < 4; j++) acc[i][j] += a[i] * b[j];
        }
        __syncthreads();
    }

    // scale logits by inv_norm and stage as S[p][k]
#pragma unroll
    for (int j = 0; j < 4; j++) {
        float iv = g_invn[n * PP + p0 + tx * 4 + j];
#pragma unroll
        for (int i = 0; i < 4; i++) u.s.S[tx * 4 + j][ty * 4 + i] = acc[i][j] * iv;
    }
    __syncthreads();

    // softmax over k (64) per p-row; 8 warps x 8 rows each
    int lane = tid & 31, wrp = tid >> 5;
    float pa = 0.f, pb = 0.f;
    for (int r8 = 0; r8 < 8; r8++) {
        int r = wrp * 8 + r8;
        float v0 = u.s.S[r][lane];
        float v1 = u.s.S[r][lane + 32];
        float m = fmaxf(v0, v1);
#pragma unroll
        for (int o = 16; o > 0; o >>= 1) m = fmaxf(m, __shfl_xor_sync(0xffffffffu, m, o));
        float e0 = __expf(v0 - m), e1 = __expf(v1 - m);
        float s = e0 + e1;
#pragma unroll
        for (int o = 16; o > 0; o >>= 1) s += __shfl_xor_sync(0xffffffffu, s, o);
        float h  = g_hmp [n * PP + p0 + r];
        float iv = g_invn[n * PP + p0 + r];
        float sc = h / s;
        float w0 = e0 * sc, w1 = e1 * sc;
        size_t base = ((size_t)n * PP + p0 + r) * KK;
        g_w2[base + lane]      = w0 * iv;
        g_w2[base + lane + 32] = w1 * iv;
        pa += w0; pb += w1;
    }
    u.s.ps[wrp][lane]      = pa;
    u.s.ps[wrp][lane + 32] = pb;
    __syncthreads();
    if (tid < 64) {
        float s = 0.f;
#pragma unroll
        for (int w = 0; w < 8; w++) s += u.s.ps[w][tid];
        g_wsp[(n * NPT + pt) * KK + tid] = s;
    }
}

// ---------------- kernel C: GEMM2 partials (split-P) -----------------------
// block = (c-tile of 128, n, p-split). Output tile [k=64][c=128] over PSP p.
// 8x4 per-thread blocking: 32 FFMA per 3 LDS.128 -> FMA-bound.
__global__ __launch_bounds__(256) void k_vlad(const float* __restrict__ x) {
    __shared__ __align__(16) float ws [CHK][68];    // [pp][k]   (68*4B = 272 = 17*16)
    __shared__ __align__(16) float xsT[CHK][132];   // [pp][c]   (132*4B = 528 = 33*16)
    int ct = blockIdx.x;            // 0..3
    int n  = blockIdx.y;            // 0..47
    int sp = blockIdx.z;            // 0..NSPLIT-1
    int c0 = ct * CT;
    int p0 = sp * PSP;
    int tid = threadIdx.x;
    int tx = tid & 31, ty = tid >> 5;   // tx -> c group (4 each), ty -> k group (8 each)

    float acc[8][4] = {};
    for (int pc = 0; pc < PSP; pc += CHK) {
        // w2 chunk: 16 p-rows x 64 k = 256 float4, 1 per thread
        {
            int pp = tid >> 4, k4 = (tid & 15) * 4;
            float4 v = *reinterpret_cast<const float4*>(
                &g_w2[((size_t)n * PP + p0 + pc + pp) * KK + k4]);
            *reinterpret_cast<float4*>(&ws[pp][k4]) = v;
        }
        // x chunk transposed: 16 p x 128 c = 512 float4-reads (along p), 2 per thread
#pragma unroll
        for (int i = tid; i < 512; i += 256) {
            int c = i >> 2, pq = (i & 3) * 4;
            float4 v = *reinterpret_cast<const float4*>(
                &x[((size_t)(n * CC + c0 + c)) * PP + p0 + pc + pq]);
            xsT[pq + 0][c] = v.x;
            xsT[pq + 1][c] = v.y;
            xsT[pq + 2][c] = v.z;
            xsT[pq + 3][c] = v.w;
        }
        __syncthreads();
#pragma unroll 4
        for (int pp = 0; pp < CHK; pp++) {
            float4 a0 = *reinterpret_cast<const float4*>(&ws[pp][ty * 8]);
            float4 a1 = *reinterpret_cast<const float4*>(&ws[pp][ty * 8 + 4]);
            float4 bv = *reinterpret_cast<const float4*>(&xsT[pp][tx * 4]);
            float a[8] = {a0.x, a0.y, a0.z, a0.w, a1.x, a1.y, a1.z, a1.w};
            float b[4] = {bv.x, bv.y, bv.z, bv.w};
#pragma unroll
            for (int i = 0; i < 8; i++)
#pragma unroll
                for (int j = 0; j < 4; j++) acc[i][j] += a[i] * b[j];
        }
        __syncthreads();
    }
    // write partial tile: 8 k-rows x float4
#pragma unroll
    for (int i = 0; i < 8; i++) {
        float4 v = make_float4(acc[i][0], acc[i][1], acc[i][2], acc[i][3]);
        size_t o = (((size_t)sp * NN + n) * KK + ty * 8 + i) * CC + c0 + tx * 4;
        *reinterpret_cast<float4*>(&g_vp[o]) = v;
    }
}

// ---------------- kernel E: reduce partials + residual + intra L2 ----------
__global__ __launch_bounds__(256) void k_norm1(const float* __restrict__ cent,
                                               float* __restrict__ out) {
    __shared__ float red[256];
    int k = blockIdx.x, n = blockIdx.y, tid = threadIdx.x;
    float wsum = 0.f;
#pragma unroll
    for (int t = 0; t < NPT; t++) wsum += g_wsp[(n * NPT + t) * KK + k];

    float t1a = 0.f, t1b = 0.f;
#pragma unroll
    for (int s = 0; s < NSPLIT; s++) {
        size_t b = (((size_t)s * NN + n) * KK + k) * CC;
        t1a += g_vp[b + tid];
        t1b += g_vp[b + tid + 256];
    }
    size_t base = (size_t)n * KC + (size_t)k * CC;
    float v1 = t1a - wsum * cent[k * CC + tid];
    float v2 = t1b - wsum * cent[k * CC + tid + 256];
    red[tid] = v1 * v1 + v2 * v2;
    __syncthreads();
    for (int o = 128; o > 0; o >>= 1) {
        if (tid < o) red[tid] += red[tid + o];
        __syncthreads();
    }
    float tot = red[0];
    float inv = 1.f / fmaxf(sqrtf(tot), 1e-12f);
    out[base + tid]       = v1 * inv;
    out[base + tid + 256] = v2 * inv;
    if (tid == 0) g_gpart[n * KK + k] = tot * inv * inv;
}

// ---------------- kernel F: global L2 normalize ----------------------------
__global__ __launch_bounds__(256) void k_norm2(float* __restrict__ out) {
    __shared__ float s[KK];
    __shared__ float ginv;
    size_t i = (size_t)blockIdx.x * 256 + threadIdx.x;
    int n = (int)(i >> 15);                    // 32768 elements per n
    if (threadIdx.x < KK) s[threadIdx.x] = g_gpart[n * KK + threadIdx.x];
    __syncthreads();
    if (threadIdx.x == 0) {
        float t = 0.f;
#pragma unroll
        for (int j = 0; j < KK; j++) t += s[j];
        ginv = 1.f / fmaxf(sqrtf(t), 1e-12f);
    }
    __syncthreads();
    out[i] *= ginv;
}

// ---------------- launch ---------------------------------------------------
extern "C" void kernel_launch(void* const* d_in, const int* in_sizes, int n_in,
                              void* d_out, int out_size) {
    const float* x      = (const float*)d_in[0];
    const float* conv_w = (const float*)d_in[1];
    const float* attn_w = (const float*)d_in[2];
    const float* attn_b = (const float*)d_in[3];
    const float* cent   = (const float*)d_in[4];
    float* out = (float*)d_out;
    (void)in_sizes; (void)n_in; (void)out_size;

    k_transpose<<<(CC * KK + 255) / 256, 256>>>(conv_w);
    k_prep<<<NN * PP / 256, 256>>>(x, attn_w, attn_b);
    k_assign<<<dim3(NPT, NN), 256>>>(x);
    k_vlad<<<dim3(CC / CT, NN, NSPLIT), 256>>>(x);
    k_norm1<<<dim3(KK, NN), 256>>>(cent, out);
    k_norm2<<<(NN * KC) / 256, 256>>>(out);
}

// round 4
// speedup vs baseline: 1.6549x; 1.3506x over previous
#include <cuda_runtime.h>
#include <math.h>

// Problem constants (fixed shapes from reference)
#define NN 48
#define CC 512
#define PP 1600      // 40*40
#define KK 64
#define KC 32768     // K*C
#define NPT 25       // P / 64 tiles (k_assign)

// k_vlad tiling
#define CT 256       // c tile
#define NSPLIT 10    // split-P factor
#define PSP 160      // P per split
#define CHK 16       // pp chunk

// ---------------- scratch (static device memory; no runtime allocs) --------
__device__ float g_w2  [(size_t)NN * PP * KK];   // w2 = softmax*hmp*invn, layout [n][p][k]
__device__ float g_wsp [NN * NPT * KK];    // partial wsum per p-tile  [n][pt][k]
__device__ float g_convT[CC * KK];         // conv_w transposed [c][k]
__device__ float g_gpart[NN * KK];         // per-(n,k) contribution to global norm^2
__device__ float g_vp  [(size_t)NSPLIT * NN * KK * CC];  // GEMM2 partials [s][n][k][c]

// ---------------- kernel P: transpose conv_w (one-time tiny) ---------------
__global__ void k_transpose(const float* __restrict__ conv_w) {
    int i = blockIdx.x * 256 + threadIdx.x;   // i = c*64 + k
    if (i < CC * KK) {
        int c = i >> 6, k = i & 63;
        g_convT[i] = conv_w[k * CC + c];
    }
}

// ---------------- kernel B: GEMM1 + fused prep (invn, heatmap) + softmax ---
// 64 threads, tile [k=64][p=64], 8x8 per thread (2x2 blocks of 4x4).
// Also accumulates per-p sum(x^2) and relu(x).aw while x streams through smem.
struct AsgG { float cws[32][64]; float xs[32][64]; };   // [cc][k], [cc][p]
struct AsgS { float S[64][65]; float ps[2][64]; };      // [p][k] logits, warp partials
union AsgU { AsgG g; AsgS s; };

__global__ __launch_bounds__(64, 8) void k_assign(const float* __restrict__ x,
                                                  const float* __restrict__ aw,
                                                  const float* __restrict__ ab) {
    __shared__ __align__(16) AsgU u;
    __shared__ float saw[CC];
    __shared__ float ivb[64], hmb[64];
    int pt = blockIdx.x, n = blockIdx.y;
    int p0 = pt * 64;
    int tid = threadIdx.x;
    int tx = tid & 7, ty = tid >> 3;          // tx -> p group, ty -> k group

    for (int i = tid; i < CC; i += 64) saw[i] = aw[i];

    float acc[2][2][4][4] = {};
    float ss = 0.f, hs = 0.f;
    for (int c0 = 0; c0 < CC; c0 += 32) {
#pragma unroll
        for (int i = tid; i < 512; i += 64) {   // conv^T chunk: [cc][k]
            int cc = i >> 4, k4 = (i & 15) * 4;
            *reinterpret_cast<float4*>(&u.g.cws[cc][k4]) =
                *reinterpret_cast<const float4*>(&g_convT[(c0 + cc) * KK + k4]);
        }
#pragma unroll
        for (int i = tid; i < 512; i += 64) {   // x chunk: [cc][p]
            int cc = i >> 4, p4 = (i & 15) * 4;
            *reinterpret_cast<float4*>(&u.g.xs[cc][p4]) =
                *reinterpret_cast<const float4*>(&x[((size_t)(n * CC + c0 + cc)) * PP + p0 + p4]);
        }
        __syncthreads();
#pragma unroll 4
        for (int cc = 0; cc < 32; cc++) {
            float4 a0 = *reinterpret_cast<const float4*>(&u.g.cws[cc][ty * 4]);
            float4 a1 = *reinterpret_cast<const float4*>(&u.g.cws[cc][32 + ty * 4]);
            float4 b0 = *reinterpret_cast<const float4*>(&u.g.xs[cc][tx * 4]);
            float4 b1 = *reinterpret_cast<const float4*>(&u.g.xs[cc][32 + tx * 4]);
            float a[2][4] = {{a0.x, a0.y, a0.z, a0.w}, {a1.x, a1.y, a1.z, a1.w}};
            float b[2][4] = {{b0.x, b0.y, b0.z, b0.w}, {b1.x, b1.y, b1.z, b1.w}};
#pragma unroll
            for (int kh = 0; kh < 2; kh++)
#pragma unroll
                for (int ph = 0; ph < 2; ph++)
#pragma unroll
                    for (int i = 0; i < 4; i++)
#pragma unroll
                        for (int j = 0; j < 4; j++)
                            acc[kh][ph][i][j] += a[kh][i] * b[ph][j];
            // fused prep: thread tid owns p = tid
            float v = u.g.xs[cc][tid];
            ss += v * v;
            hs += fmaxf(v, 0.f) * saw[c0 + cc];
        }
        __syncthreads();
    }

    // finish prep for p = tid
    ivb[tid] = 1.f / fmaxf(sqrtf(ss), 1e-12f);
    hmb[tid] = fmaxf(hs + ab[0], 0.f);
    __syncthreads();

    // stage logits (scaled by inv_norm) as S[p][k]
#pragma unroll
    for (int kh = 0; kh < 2; kh++)
#pragma unroll
        for (int ph = 0; ph < 2; ph++)
#pragma unroll
            for (int j = 0; j < 4; j++) {
                int p = ph * 32 + tx * 4 + j;
                float iv = ivb[p];
#pragma unroll
                for (int i = 0; i < 4; i++)
                    u.s.S[p][kh * 32 + ty * 4 + i] = acc[kh][ph][i][j] * iv;
            }
    __syncthreads();

    // softmax over k (64) per p-row; 2 warps x 32 rows each
    int lane = tid & 31, wrp = tid >> 5;
    float pa = 0.f, pb = 0.f;
    for (int r8 = 0; r8 < 32; r8++) {
        int r = wrp * 32 + r8;
        float v0 = u.s.S[r][lane];
        float v1 = u.s.S[r][lane + 32];
        float m = fmaxf(v0, v1);
#pragma unroll
        for (int o = 16; o > 0; o >>= 1) m = fmaxf(m, __shfl_xor_sync(0xffffffffu, m, o));
        float e0 = __expf(v0 - m), e1 = __expf(v1 - m);
        float s = e0 + e1;
#pragma unroll
        for (int o = 16; o > 0; o >>= 1) s += __shfl_xor_sync(0xffffffffu, s, o);
        float h  = hmb[r];
        float iv = ivb[r];
        float sc = h / s;
        float w0 = e0 * sc, w1 = e1 * sc;
        size_t base = ((size_t)n * PP + p0 + r) * KK;
        g_w2[base + lane]      = w0 * iv;
        g_w2[base + lane + 32] = w1 * iv;
        pa += w0; pb += w1;
    }
    u.s.ps[wrp][lane]      = pa;
    u.s.ps[wrp][lane + 32] = pb;
    __syncthreads();
    if (tid < 64) {
        g_wsp[(n * NPT + pt) * KK + tid] = u.s.ps[0][tid] + u.s.ps[1][tid];
    }
}

// ---------------- kernel C: GEMM2 partials (split-P) -----------------------
// block = (c-tile of 256, n, p-split). Output tile [k=64][c=256] over PSP p.
// 8x8 per-thread blocking (2x2 blocks of 4x4): 64 FFMA per 64B LDS.
__global__ __launch_bounds__(256, 2) void k_vlad(const float* __restrict__ x) {
    __shared__ __align__(16) float ws [CHK][68];    // [pp][k]
    __shared__ __align__(16) float xsT[CHK][260];   // [pp][c]
    int ct = blockIdx.x;            // 0..1
    int n  = blockIdx.y;            // 0..47
    int sp = blockIdx.z;            // 0..NSPLIT-1
    int c0 = ct * CT;
    int p0 = sp * PSP;
    int tid = threadIdx.x;
    int tx = tid & 31, ty = tid >> 5;   // tx -> c group, ty -> k group

    float acc[2][2][4][4] = {};
    for (int pc = 0; pc < PSP; pc += CHK) {
        // w2 chunk: 16 p-rows x 64 k = 256 float4, 1 per thread
        {
            int pp = tid >> 4, k4 = (tid & 15) * 4;
            *reinterpret_cast<float4*>(&ws[pp][k4]) = *reinterpret_cast<const float4*>(
                &g_w2[((size_t)n * PP + p0 + pc + pp) * KK + k4]);
        }
        // x chunk transposed: 16 p x 256 c; float4 along p, 4 per thread
#pragma unroll
        for (int i = tid; i < 1024; i += 256) {
            int c = i >> 2, pq = (i & 3) * 4;
            float4 v = *reinterpret_cast<const float4*>(
                &x[((size_t)(n * CC + c0 + c)) * PP + p0 + pc + pq]);
            xsT[pq + 0][c] = v.x;
            xsT[pq + 1][c] = v.y;
            xsT[pq + 2][c] = v.z;
            xsT[pq + 3][c] = v.w;
        }
        __syncthreads();
#pragma unroll
        for (int pp = 0; pp < CHK; pp++) {
            float4 a0 = *reinterpret_cast<const float4*>(&ws [pp][ty * 4]);
            float4 a1 = *reinterpret_cast<const float4*>(&ws [pp][32 + ty * 4]);
            float4 b0 = *reinterpret_cast<const float4*>(&xsT[pp][tx * 4]);
            float4 b1 = *reinterpret_cast<const float4*>(&xsT[pp][128 + tx * 4]);
            float a[2][4] = {{a0.x, a0.y, a0.z, a0.w}, {a1.x, a1.y, a1.z, a1.w}};
            float b[2][4] = {{b0.x, b0.y, b0.z, b0.w}, {b1.x, b1.y, b1.z, b1.w}};
#pragma unroll
            for (int kh = 0; kh < 2; kh++)
#pragma unroll
                for (int ch = 0; ch < 2; ch++)
#pragma unroll
                    for (int i = 0; i < 4; i++)
#pragma unroll
                        for (int j = 0; j < 4; j++)
                            acc[kh][ch][i][j] += a[kh][i] * b[ch][j];
        }
        __syncthreads();
    }
    // write partial tiles
#pragma unroll
    for (int kh = 0; kh < 2; kh++)
#pragma unroll
        for (int ch = 0; ch < 2; ch++)
#pragma unroll
            for (int i = 0; i < 4; i++) {
                float4 v = make_float4(acc[kh][ch][i][0], acc[kh][ch][i][1],
                                       acc[kh][ch][i][2], acc[kh][ch][i][3]);
                size_t o = (((size_t)sp * NN + n) * KK + kh * 32 + ty * 4 + i) * CC
                         + c0 + ch * 128 + tx * 4;
                *reinterpret_cast<float4*>(&g_vp[o]) = v;
            }
}

// ---------------- kernel E: reduce partials + residual + intra L2 ----------
__global__ __launch_bounds__(256) void k_norm1(const float* __restrict__ cent,
                                               float* __restrict__ out) {
    __shared__ float red[256];
    int k = blockIdx.x, n = blockIdx.y, tid = threadIdx.x;
    float wsum = 0.f;
#pragma unroll
    for (int t = 0; t < NPT; t++) wsum += g_wsp[(n * NPT + t) * KK + k];

    float t1a = 0.f, t1b = 0.f;
#pragma unroll
    for (int s = 0; s < NSPLIT; s++) {
        size_t b = (((size_t)s * NN + n) * KK + k) * CC;
        t1a += g_vp[b + tid];
        t1b += g_vp[b + tid + 256];
    }
    size_t base = (size_t)n * KC + (size_t)k * CC;
    float v1 = t1a - wsum * cent[k * CC + tid];
    float v2 = t1b - wsum * cent[k * CC + tid + 256];
    red[tid] = v1 * v1 + v2 * v2;
    __syncthreads();
    for (int o = 128; o > 0; o >>= 1) {
        if (tid < o) red[tid] += red[tid + o];
        __syncthreads();
    }
    float tot = red[0];
    float inv = 1.f / fmaxf(sqrtf(tot), 1e-12f);
    out[base + tid]       = v1 * inv;
    out[base + tid + 256] = v2 * inv;
    if (tid == 0) g_gpart[n * KK + k] = tot * inv * inv;
}

// ---------------- kernel F: global L2 normalize ----------------------------
__global__ __launch_bounds__(256) void k_norm2(float* __restrict__ out) {
    __shared__ float s[KK];
    __shared__ float ginv;
    size_t i = (size_t)blockIdx.x * 256 + threadIdx.x;
    int n = (int)(i >> 15);                    // 32768 elements per n
    if (threadIdx.x < KK) s[threadIdx.x] = g_gpart[n * KK + threadIdx.x];
    __syncthreads();
    if (threadIdx.x == 0) {
        float t = 0.f;
#pragma unroll
        for (int j = 0; j < KK; j++) t += s[j];
        ginv = 1.f / fmaxf(sqrtf(t), 1e-12f);
    }
    __syncthreads();
    out[i] *= ginv;
}

// ---------------- launch ---------------------------------------------------
extern "C" void kernel_launch(void* const* d_in, const int* in_sizes, int n_in,
                              void* d_out, int out_size) {
    const float* x      = (const float*)d_in[0];
    const float* conv_w = (const float*)d_in[1];
    const float* attn_w = (const float*)d_in[2];
    const float* attn_b = (const float*)d_in[3];
    const float* cent   = (const float*)d_in[4];
    float* out = (float*)d_out;
    (void)in_sizes; (void)n_in; (void)out_size;

    k_transpose<<<(CC * KK + 255) / 256, 256>>>(conv_w);
    k_assign<<<dim3(NPT, NN), 64>>>(x, attn_w, attn_b);
    k_vlad<<<dim3(CC / CT, NN, NSPLIT), 256>>>(x);
    k_norm1<<<dim3(KK, NN), 256>>>(cent, out);
    k_norm2<<<(NN * KC) / 256, 256>>>(out);
}

// round 6
// speedup vs baseline: 1.7424x; 1.0529x over previous
#include <cuda_runtime.h>
#include <math.h>
#include <stdint.h>

// Problem constants
#define NN 48
#define CC 512
#define PP 1600      // 40*40
#define KK 64
#define KC 32768     // K*C
#define NPT 25       // P / 64 tiles (k_assign)

// k_vlad tiling
#define CT 256       // c tile
#define NSPLIT 5     // split-P factor
#define PSP 320      // P per split
#define CHK 16       // pp chunk

// k_assign chunking
#define ACK 16       // c chunk
#define NCH (CC / ACK)   // 32

// ---------------- scratch ---------------------------------------------------
__device__ float g_w2  [(size_t)NN * PP * KK];   // w2 = softmax*hmp*invn, [n][p][k]
__device__ float g_wsp [NN * NPT * KK];          // partial wsum [n][pt][k]
__device__ float g_convT[CC * KK];               // conv_w transposed [c][k]
__device__ float g_gpart[NN * KK];
__device__ float g_vp  [(size_t)NSPLIT * NN * KK * CC];  // GEMM2 partials

// ---------------- helpers ----------------------------------------------------
__device__ __forceinline__ uint32_t s2u32(const void* p) {
    uint32_t a;
    asm("{ .reg .u64 t; cvta.to.shared.u64 t, %1; cvt.u32.u64 %0, t; }" : "=r"(a) : "l"(p));
    return a;
}
__device__ __forceinline__ void cpa16(uint32_t d, const void* s) {
    asm volatile("cp.async.cg.shared.global [%0], [%1], 16;" :: "r"(d), "l"(s) : "memory");
}
#define CP_COMMIT() asm volatile("cp.async.commit_group;" ::: "memory")
#define CP_WAIT(n)  asm volatile("cp.async.wait_group %0;" :: "n"(n) : "memory")

// ---------------- kernel P: transpose conv_w --------------------------------
__global__ void k_transpose(const float* __restrict__ conv_w) {
    int i = blockIdx.x * 256 + threadIdx.x;
    if (i < CC * KK) {
        int c = i >> 6, k = i & 63;
        g_convT[i] = conv_w[k * CC + c];
    }
}

// ---------------- kernel B: GEMM1 + fused prep + softmax --------------------
// 64 threads, tile [k=64][p=64], 8x8 per thread, cp.async double-buffered.
struct AsgG { float cw[2][ACK][64]; float xs[2][ACK][64]; };  // 16 KB
struct AsgS { float S[64][65]; float ps[2][64]; };            // 17.2 KB
union AsgU { AsgG g; AsgS s; };

__global__ __launch_bounds__(64, 8) void k_assign(const float* __restrict__ x,
                                                  const float* __restrict__ aw,
                                                  const float* __restrict__ ab) {
    __shared__ __align__(16) AsgU u;
    __shared__ float saw[CC];
    __shared__ float ivb[64], hmb[64];
    int pt = blockIdx.x, n = blockIdx.y;
    int p0 = pt * 64;
    int tid = threadIdx.x;
    int tx = tid & 7, ty = tid >> 3;

    for (int i = tid; i < CC; i += 64) saw[i] = aw[i];

    // issue one 16-c chunk into buffer b
#define ISSUE(ch, b) do {                                                      \
        int _c0 = (ch) * ACK;                                                  \
        _Pragma("unroll")                                                      \
        for (int j = 0; j < 4; j++) {                                          \
            int i = tid + j * 64;                                              \
            int cc = i >> 4, seg = (i & 15) * 4;                               \
            cpa16(s2u32(&u.g.cw[b][cc][seg]), &g_convT[(_c0 + cc) * KK + seg]); \
            cpa16(s2u32(&u.g.xs[b][cc][seg]),                                  \
                  &x[((size_t)(n * CC + _c0 + cc)) * PP + p0 + seg]);          \
        }                                                                      \
    } while (0)

    float acc[2][2][4][4] = {};
    float ss = 0.f, hs = 0.f;

    ISSUE(0, 0); CP_COMMIT();
    for (int ch = 0; ch < NCH; ch++) {
        int b = ch & 1;
        if (ch < NCH - 1) { ISSUE(ch + 1, b ^ 1); CP_COMMIT(); CP_WAIT(1); }
        else CP_WAIT(0);
        __syncthreads();
#pragma unroll 4
        for (int cc = 0; cc < ACK; cc++) {
            float4 a0 = *reinterpret_cast<const float4*>(&u.g.cw[b][cc][ty * 4]);
            float4 a1 = *reinterpret_cast<const float4*>(&u.g.cw[b][cc][32 + ty * 4]);
            float4 b0 = *reinterpret_cast<const float4*>(&u.g.xs[b][cc][tx * 4]);
            float4 b1 = *reinterpret_cast<const float4*>(&u.g.xs[b][cc][32 + tx * 4]);
            float a[2][4] = {{a0.x, a0.y, a0.z, a0.w}, {a1.x, a1.y, a1.z, a1.w}};
            float bb[2][4] = {{b0.x, b0.y, b0.z, b0.w}, {b1.x, b1.y, b1.z, b1.w}};
#pragma unroll
            for (int kh = 0; kh < 2; kh++)
#pragma unroll
                for (int ph = 0; ph < 2; ph++)
#pragma unroll
                    for (int i = 0; i < 4; i++)
#pragma unroll
                        for (int j = 0; j < 4; j++)
                            acc[kh][ph][i][j] += a[kh][i] * bb[ph][j];
            float v = u.g.xs[b][cc][tid];
            ss += v * v;
            hs += fmaxf(v, 0.f) * saw[ch * ACK + cc];
        }
        __syncthreads();
    }

    ivb[tid] = 1.f / fmaxf(sqrtf(ss), 1e-12f);
    hmb[tid] = fmaxf(hs + ab[0], 0.f);
    __syncthreads();

    // stage logits (scaled by inv_norm) as S[p][k]
#pragma unroll
    for (int kh = 0; kh < 2; kh++)
#pragma unroll
        for (int ph = 0; ph < 2; ph++)
#pragma unroll
            for (int j = 0; j < 4; j++) {
                int p = ph * 32 + tx * 4 + j;
                float iv = ivb[p];
#pragma unroll
                for (int i = 0; i < 4; i++)
                    u.s.S[p][kh * 32 + ty * 4 + i] = acc[kh][ph][i][j] * iv;
            }
    __syncthreads();

    // softmax over k (64) per p-row; 2 warps x 32 rows each
    int lane = tid & 31, wrp = tid >> 5;
    float pa = 0.f, pb = 0.f;
    for (int r8 = 0; r8 < 32; r8++) {
        int r = wrp * 32 + r8;
        float v0 = u.s.S[r][lane];
        float v1 = u.s.S[r][lane + 32];
        float m = fmaxf(v0, v1);
#pragma unroll
        for (int o = 16; o > 0; o >>= 1) m = fmaxf(m, __shfl_xor_sync(0xffffffffu, m, o));
        float e0 = __expf(v0 - m), e1 = __expf(v1 - m);
        float s = e0 + e1;
#pragma unroll
        for (int o = 16; o > 0; o >>= 1) s += __shfl_xor_sync(0xffffffffu, s, o);
        float h  = hmb[r];
        float iv = ivb[r];
        float sc = h / s;
        float w0 = e0 * sc, w1 = e1 * sc;
        size_t base = ((size_t)n * PP + p0 + r) * KK;
        g_w2[base + lane]      = w0 * iv;
        g_w2[base + lane + 32] = w1 * iv;
        pa += w0; pb += w1;
    }
    u.s.ps[wrp][lane]      = pa;
    u.s.ps[wrp][lane + 32] = pb;
    __syncthreads();
    if (tid < 64)
        g_wsp[(n * NPT + pt) * KK + tid] = u.s.ps[0][tid] + u.s.ps[1][tid];
}

// ---------------- kernel C: GEMM2 partials (split-P), reg-prefetched --------
__global__ __launch_bounds__(256, 2) void k_vlad(const float* __restrict__ x) {
    __shared__ __align__(16) float ws [CHK][68];    // [pp][k]
    __shared__ __align__(16) float xsT[CHK][260];   // [pp][c]
    int ct = blockIdx.x;            // 0..1
    int n  = blockIdx.y;            // 0..47
    int sp = blockIdx.z;            // 0..NSPLIT-1
    int c0 = ct * CT;
    int p0 = sp * PSP;
    int tid = threadIdx.x;
    int tx = tid & 31, ty = tid >> 5;

    int cbase = (tid >> 2);            // 0..63
    int pq    = (tid & 3) * 4;
    const float* xrow = x + ((size_t)(n * CC + c0 + cbase)) * PP + p0 + pq;

    float4 rx[4];
#define XLOAD(pc) do {                                                         \
        _Pragma("unroll")                                                      \
        for (int q = 0; q < 4; q++)                                            \
            rx[q] = *reinterpret_cast<const float4*>(xrow + (size_t)q * 64 * PP + (pc)); \
    } while (0)

    float acc[2][2][4][4] = {};
    XLOAD(0);
    for (int pc = 0; pc < PSP; pc += CHK) {
        // w2 chunk: 16 p-rows x 64 k = 256 float4, 1 per thread
        {
            int pp = tid >> 4, k4 = (tid & 15) * 4;
            *reinterpret_cast<float4*>(&ws[pp][k4]) = *reinterpret_cast<const float4*>(
                &g_w2[((size_t)n * PP + p0 + pc + pp) * KK + k4]);
        }
        // x chunk transposed: STS from prefetched regs
#pragma unroll
        for (int q = 0; q < 4; q++) {
            int c = cbase + q * 64;
            xsT[pq + 0][c] = rx[q].x;
            xsT[pq + 1][c] = rx[q].y;
            xsT[pq + 2][c] = rx[q].z;
            xsT[pq + 3][c] = rx[q].w;
        }
        if (pc + CHK < PSP) XLOAD(pc + CHK);
        __syncthreads();
#pragma unroll
        for (int pp = 0; pp < CHK; pp++) {
            float4 a0 = *reinterpret_cast<const float4*>(&ws [pp][ty * 4]);
            float4 a1 = *reinterpret_cast<const float4*>(&ws [pp][32 + ty * 4]);
            float4 b0 = *reinterpret_cast<const float4*>(&xsT[pp][tx * 4]);
            float4 b1 = *reinterpret_cast<const float4*>(&xsT[pp][128 + tx * 4]);
            float a[2][4] = {{a0.x, a0.y, a0.z, a0.w}, {a1.x, a1.y, a1.z, a1.w}};
            float b[2][4] = {{b0.x, b0.y, b0.z, b0.w}, {b1.x, b1.y, b1.z, b1.w}};
#pragma unroll
            for (int kh = 0; kh < 2; kh++)
#pragma unroll
                for (int chh = 0; chh < 2; chh++)
#pragma unroll
                    for (int i = 0; i < 4; i++)
#pragma unroll
                        for (int j = 0; j < 4; j++)
                            acc[kh][chh][i][j] += a[kh][i] * b[chh][j];
        }
        __syncthreads();
    }
    // write partial tiles
#pragma unroll
    for (int kh = 0; kh < 2; kh++)
#pragma unroll
        for (int chh = 0; chh < 2; chh++)
#pragma unroll
            for (int i = 0; i < 4; i++) {
                float4 v = make_float4(acc[kh][chh][i][0], acc[kh][chh][i][1],
                                       acc[kh][chh][i][2], acc[kh][chh][i][3]);
                size_t o = (((size_t)sp * NN + n) * KK + kh * 32 + ty * 4 + i) * CC
                         + c0 + chh * 128 + tx * 4;
                *reinterpret_cast<float4*>(&g_vp[o]) = v;
            }
}

// ---------------- kernel E: reduce partials + residual + intra L2 ----------
__global__ __launch_bounds__(256) void k_norm1(const float* __restrict__ cent,
                                               float* __restrict__ out) {
    __shared__ float red[256];
    int k = blockIdx.x, n = blockIdx.y, tid = threadIdx.x;
    float wsum = 0.f;
#pragma unroll
    for (int t = 0; t < NPT; t++) wsum += g_wsp[(n * NPT + t) * KK + k];

    float t1a = 0.f, t1b = 0.f;
#pragma unroll
    for (int s = 0; s < NSPLIT; s++) {
        size_t b = (((size_t)s * NN + n) * KK + k) * CC;
        t1a += g_vp[b + tid];
        t1b += g_vp[b + tid + 256];
    }
    size_t base = (size_t)n * KC + (size_t)k * CC;
    float v1 = t1a - wsum * cent[k * CC + tid];
    float v2 = t1b - wsum * cent[k * CC + tid + 256];
    red[tid] = v1 * v1 + v2 * v2;
    __syncthreads();
    for (int o = 128; o > 0; o >>= 1) {
        if (tid < o) red[tid] += red[tid + o];
        __syncthreads();
    }
    float tot = red[0];
    float inv = 1.f / fmaxf(sqrtf(tot), 1e-12f);
    out[base + tid]       = v1 * inv;
    out[base + tid + 256] = v2 * inv;
    if (tid == 0) g_gpart[n * KK + k] = tot * inv * inv;
}

// ---------------- kernel F: global L2 normalize ------------------------------
__global__ __launch_bounds__(256) void k_norm2(float* __restrict__ out) {
    __shared__ float s[KK];
    __shared__ float ginv;
    size_t i = (size_t)blockIdx.x * 256 + threadIdx.x;
    int n = (int)(i >> 15);
    if (threadIdx.x < KK) s[threadIdx.x] = g_gpart[n * KK + threadIdx.x];
    __syncthreads();
    if (threadIdx.x == 0) {
        float t = 0.f;
#pragma unroll
        for (int j = 0; j < KK; j++) t += s[j];
        ginv = 1.f / fmaxf(sqrtf(t), 1e-12f);
    }
    __syncthreads();
    out[i] *= ginv;
}

// ---------------- launch -----------------------------------------------------
extern "C" void kernel_launch(void* const* d_in, const int* in_sizes, int n_in,
                              void* d_out, int out_size) {
    const float* x      = (const float*)d_in[0];
    const float* conv_w = (const float*)d_in[1];
    const float* attn_w = (const float*)d_in[2];
    const float* attn_b = (const float*)d_in[3];
    const float* cent   = (const float*)d_in[4];
    float* out = (float*)d_out;
    (void)in_sizes; (void)n_in; (void)out_size;

    k_transpose<<<(CC * KK + 255) / 256, 256>>>(conv_w);
    k_assign<<<dim3(NPT, NN), 64>>>(x, attn_w, attn_b);
    k_vlad<<<dim3(CC / CT, NN, NSPLIT), 256>>>(x);
    k_norm1<<<dim3(KK, NN), 256>>>(cent, out);
    k_norm2<<<(NN * KC) / 256, 256>>>(out);
}

// round 7
// speedup vs baseline: 1.9133x; 1.0981x over previous
#include <cuda_runtime.h>
#include <math.h>
#include <stdint.h>

// Problem constants
#define NN 48
#define CC 512
#define PP 1600      // 40*40
#define KK 64
#define KC 32768     // K*C
#define NPT 25       // P / 64 tiles (k_assign)

// k_vlad tiling
#define CT 256       // c tile
#define NSPLIT 3     // split-P factor -> 2*48*3 = 288 CTAs = 1 wave @ 2 CTA/SM
#define CHK 16       // pp chunk

// k_assign chunking
#define ACK 16       // c chunk
#define NCH (CC / ACK)   // 32

// ---------------- scratch ---------------------------------------------------
__device__ float g_w2  [(size_t)NN * PP * KK];   // w2 = softmax*hmp*invn, [n][p][k]
__device__ float g_wsp [NN * NPT * KK];          // partial wsum [n][pt][k]
__device__ float g_convT[CC * KK];               // conv_w transposed [c][k]
__device__ float g_gpart[NN * KK];
__device__ float g_vp  [(size_t)NSPLIT * NN * KK * CC];  // GEMM2 partials

// ---------------- helpers ----------------------------------------------------
__device__ __forceinline__ uint32_t s2u32(const void* p) {
    uint32_t a;
    asm("{ .reg .u64 t; cvta.to.shared.u64 t, %1; cvt.u32.u64 %0, t; }" : "=r"(a) : "l"(p));
    return a;
}
__device__ __forceinline__ void cpa16(uint32_t d, const void* s) {
    asm volatile("cp.async.cg.shared.global [%0], [%1], 16;" :: "r"(d), "l"(s) : "memory");
}
#define CP_COMMIT() asm volatile("cp.async.commit_group;" ::: "memory")
#define CP_WAIT(n)  asm volatile("cp.async.wait_group %0;" :: "n"(n) : "memory")

// ---------------- kernel P: transpose conv_w --------------------------------
__global__ void k_transpose(const float* __restrict__ conv_w) {
    int i = blockIdx.x * 256 + threadIdx.x;
    if (i < CC * KK) {
        int c = i >> 6, k = i & 63;
        g_convT[i] = conv_w[k * CC + c];
    }
}

// ---------------- kernel B: GEMM1 + fused prep + softmax --------------------
// 64 threads, tile [k=64][p=64], 8x8 per thread, cp.async double-buffered.
struct AsgG { float cw[2][ACK][64]; float xs[2][ACK][64]; };  // 16 KB
struct AsgS { float S[64][65]; float ps[2][64]; };            // 17.2 KB
union AsgU { AsgG g; AsgS s; };

__global__ __launch_bounds__(64, 8) void k_assign(const float* __restrict__ x,
                                                  const float* __restrict__ aw,
                                                  const float* __restrict__ ab) {
    __shared__ __align__(16) AsgU u;
    __shared__ float saw[CC];
    __shared__ float ivb[64], hmb[64];
    int pt = blockIdx.x, n = blockIdx.y;
    int p0 = pt * 64;
    int tid = threadIdx.x;
    int tx = tid & 7, ty = tid >> 3;

    for (int i = tid; i < CC; i += 64) saw[i] = aw[i];

    // issue one 16-c chunk into buffer b
#define ISSUE(ch, b) do {                                                      \
        int _c0 = (ch) * ACK;                                                  \
        _Pragma("unroll")                                                      \
        for (int j = 0; j < 4; j++) {                                          \
            int i = tid + j * 64;                                              \
            int cc = i >> 4, seg = (i & 15) * 4;                               \
            cpa16(s2u32(&u.g.cw[b][cc][seg]), &g_convT[(_c0 + cc) * KK + seg]); \
            cpa16(s2u32(&u.g.xs[b][cc][seg]),                                  \
                  &x[((size_t)(n * CC + _c0 + cc)) * PP + p0 + seg]);          \
        }                                                                      \
    } while (0)

    float acc[2][2][4][4] = {};
    float ss = 0.f, hs = 0.f;

    ISSUE(0, 0); CP_COMMIT();
    for (int ch = 0; ch < NCH; ch++) {
        int b = ch & 1;
        if (ch < NCH - 1) { ISSUE(ch + 1, b ^ 1); CP_COMMIT(); CP_WAIT(1); }
        else CP_WAIT(0);
        __syncthreads();
#pragma unroll 4
        for (int cc = 0; cc < ACK; cc++) {
            float4 a0 = *reinterpret_cast<const float4*>(&u.g.cw[b][cc][ty * 4]);
            float4 a1 = *reinterpret_cast<const float4*>(&u.g.cw[b][cc][32 + ty * 4]);
            float4 b0 = *reinterpret_cast<const float4*>(&u.g.xs[b][cc][tx * 4]);
            float4 b1 = *reinterpret_cast<const float4*>(&u.g.xs[b][cc][32 + tx * 4]);
            float a[2][4] = {{a0.x, a0.y, a0.z, a0.w}, {a1.x, a1.y, a1.z, a1.w}};
            float bb[2][4] = {{b0.x, b0.y, b0.z, b0.w}, {b1.x, b1.y, b1.z, b1.w}};
#pragma unroll
            for (int kh = 0; kh < 2; kh++)
#pragma unroll
                for (int ph = 0; ph < 2; ph++)
#pragma unroll
                    for (int i = 0; i < 4; i++)
#pragma unroll
                        for (int j = 0; j < 4; j++)
                            acc[kh][ph][i][j] += a[kh][i] * bb[ph][j];
            float v = u.g.xs[b][cc][tid];
            ss += v * v;
            hs += fmaxf(v, 0.f) * saw[ch * ACK + cc];
        }
        __syncthreads();
    }

    ivb[tid] = 1.f / fmaxf(sqrtf(ss), 1e-12f);
    hmb[tid] = fmaxf(hs + ab[0], 0.f);
    __syncthreads();

    // stage logits (scaled by inv_norm) as S[p][k]
#pragma unroll
    for (int kh = 0; kh < 2; kh++)
#pragma unroll
        for (int ph = 0; ph < 2; ph++)
#pragma unroll
            for (int j = 0; j < 4; j++) {
                int p = ph * 32 + tx * 4 + j;
                float iv = ivb[p];
#pragma unroll
                for (int i = 0; i < 4; i++)
                    u.s.S[p][kh * 32 + ty * 4 + i] = acc[kh][ph][i][j] * iv;
            }
    __syncthreads();

    // softmax over k (64) per p-row; 2 warps x 32 rows each
    int lane = tid & 31, wrp = tid >> 5;
    float pa = 0.f, pb = 0.f;
    for (int r8 = 0; r8 < 32; r8++) {
        int r = wrp * 32 + r8;
        float v0 = u.s.S[r][lane];
        float v1 = u.s.S[r][lane + 32];
        float m = fmaxf(v0, v1);
#pragma unroll
        for (int o = 16; o > 0; o >>= 1) m = fmaxf(m, __shfl_xor_sync(0xffffffffu, m, o));
        float e0 = __expf(v0 - m), e1 = __expf(v1 - m);
        float s = e0 + e1;
#pragma unroll
        for (int o = 16; o > 0; o >>= 1) s += __shfl_xor_sync(0xffffffffu, s, o);
        float h  = hmb[r];
        float iv = ivb[r];
        float sc = h / s;
        float w0 = e0 * sc, w1 = e1 * sc;
        size_t base = ((size_t)n * PP + p0 + r) * KK;
        g_w2[base + lane]      = w0 * iv;
        g_w2[base + lane + 32] = w1 * iv;
        pa += w0; pb += w1;
    }
    u.s.ps[wrp][lane]      = pa;
    u.s.ps[wrp][lane + 32] = pb;
    __syncthreads();
    if (tid < 64)
        g_wsp[(n * NPT + pt) * KK + tid] = u.s.ps[0][tid] + u.s.ps[1][tid];
}

// ---------------- kernel C: GEMM2 partials (split-P), reg-prefetched --------
// Uneven splits: sp0 = 544 p, sp1/sp2 = 528 p. grid 2*48*3 = 288 = 1 wave.
__global__ __launch_bounds__(256, 2) void k_vlad(const float* __restrict__ x) {
    __shared__ __align__(16) float ws [CHK][68];    // [pp][k]
    __shared__ __align__(16) float xsT[CHK][260];   // [pp][c]
    int ct = blockIdx.x;            // 0..1
    int n  = blockIdx.y;            // 0..47
    int sp = blockIdx.z;            // 0..2
    int c0 = ct * CT;
    int p0   = (sp == 0) ? 0   : 544 + (sp - 1) * 528;
    int plen = (sp == 0) ? 544 : 528;
    int tid = threadIdx.x;
    int tx = tid & 31, ty = tid >> 5;

    int cbase = (tid >> 2);            // 0..63
    int pq    = (tid & 3) * 4;
    const float* xrow = x + ((size_t)(n * CC + c0 + cbase)) * PP + p0 + pq;
    const float* wrow = g_w2 + ((size_t)n * PP + p0 + (tid >> 4)) * KK + (tid & 15) * 4;

    float4 rx[4], rw;
#define PLOAD(pc) do {                                                         \
        _Pragma("unroll")                                                      \
        for (int q = 0; q < 4; q++)                                            \
            rx[q] = *reinterpret_cast<const float4*>(xrow + (size_t)q * 64 * PP + (pc)); \
        rw = *reinterpret_cast<const float4*>(wrow + (size_t)(pc) * KK);       \
    } while (0)

    float acc[2][2][4][4] = {};
    PLOAD(0);
    for (int pc = 0; pc < plen; pc += CHK) {
        // stage from prefetched regs
        {
            int pp = tid >> 4, k4 = (tid & 15) * 4;
            *reinterpret_cast<float4*>(&ws[pp][k4]) = rw;
        }
#pragma unroll
        for (int q = 0; q < 4; q++) {
            int c = cbase + q * 64;
            xsT[pq + 0][c] = rx[q].x;
            xsT[pq + 1][c] = rx[q].y;
            xsT[pq + 2][c] = rx[q].z;
            xsT[pq + 3][c] = rx[q].w;
        }
        if (pc + CHK < plen) PLOAD(pc + CHK);
        __syncthreads();
#pragma unroll
        for (int pp = 0; pp < CHK; pp++) {
            float4 a0 = *reinterpret_cast<const float4*>(&ws [pp][ty * 4]);
            float4 a1 = *reinterpret_cast<const float4*>(&ws [pp][32 + ty * 4]);
            float4 b0 = *reinterpret_cast<const float4*>(&xsT[pp][tx * 4]);
            float4 b1 = *reinterpret_cast<const float4*>(&xsT[pp][128 + tx * 4]);
            float a[2][4] = {{a0.x, a0.y, a0.z, a0.w}, {a1.x, a1.y, a1.z, a1.w}};
            float b[2][4] = {{b0.x, b0.y, b0.z, b0.w}, {b1.x, b1.y, b1.z, b1.w}};
#pragma unroll
            for (int kh = 0; kh < 2; kh++)
#pragma unroll
                for (int chh = 0; chh < 2; chh++)
#pragma unroll
                    for (int i = 0; i < 4; i++)
#pragma unroll
                        for (int j = 0; j < 4; j++)
                            acc[kh][chh][i][j] += a[kh][i] * b[chh][j];
        }
        __syncthreads();
    }
    // write partial tiles
#pragma unroll
    for (int kh = 0; kh < 2; kh++)
#pragma unroll
        for (int chh = 0; chh < 2; chh++)
#pragma unroll
            for (int i = 0; i < 4; i++) {
                float4 v = make_float4(acc[kh][chh][i][0], acc[kh][chh][i][1],
                                       acc[kh][chh][i][2], acc[kh][chh][i][3]);
                size_t o = (((size_t)sp * NN + n) * KK + kh * 32 + ty * 4 + i) * CC
                         + c0 + chh * 128 + tx * 4;
                *reinterpret_cast<float4*>(&g_vp[o]) = v;
            }
}

// ---------------- kernel E: reduce partials + residual + intra L2 ----------
__global__ __launch_bounds__(256) void k_norm1(const float* __restrict__ cent,
                                               float* __restrict__ out) {
    __shared__ float red[256];
    int k = blockIdx.x, n = blockIdx.y, tid = threadIdx.x;
    float wsum = 0.f;
#pragma unroll
    for (int t = 0; t < NPT; t++) wsum += g_wsp[(n * NPT + t) * KK + k];

    float t1a = 0.f, t1b = 0.f;
#pragma unroll
    for (int s = 0; s < NSPLIT; s++) {
        size_t b = (((size_t)s * NN + n) * KK + k) * CC;
        t1a += g_vp[b + tid];
        t1b += g_vp[b + tid + 256];
    }
    size_t base = (size_t)n * KC + (size_t)k * CC;
    float v1 = t1a - wsum * cent[k * CC + tid];
    float v2 = t1b - wsum * cent[k * CC + tid + 256];
    red[tid] = v1 * v1 + v2 * v2;
    __syncthreads();
    for (int o = 128; o > 0; o >>= 1) {
        if (tid < o) red[tid] += red[tid + o];
        __syncthreads();
    }
    float tot = red[0];
    float inv = 1.f / fmaxf(sqrtf(tot), 1e-12f);
    out[base + tid]       = v1 * inv;
    out[base + tid + 256] = v2 * inv;
    if (tid == 0) g_gpart[n * KK + k] = tot * inv * inv;
}

// ---------------- kernel F: global L2 normalize ------------------------------
__global__ __launch_bounds__(256) void k_norm2(float* __restrict__ out) {
    __shared__ float s[KK];
    __shared__ float ginv;
    size_t i = (size_t)blockIdx.x * 256 + threadIdx.x;
    int n = (int)(i >> 15);
    if (threadIdx.x < KK) s[threadIdx.x] = g_gpart[n * KK + threadIdx.x];
    __syncthreads();
    if (threadIdx.x == 0) {
        float t = 0.f;
#pragma unroll
        for (int j = 0; j < KK; j++) t += s[j];
        ginv = 1.f / fmaxf(sqrtf(t), 1e-12f);
    }
    __syncthreads();
    out[i] *= ginv;
}

// ---------------- launch -----------------------------------------------------
extern "C" void kernel_launch(void* const* d_in, const int* in_sizes, int n_in,
                              void* d_out, int out_size) {
    const float* x      = (const float*)d_in[0];
    const float* conv_w = (const float*)d_in[1];
    const float* attn_w = (const float*)d_in[2];
    const float* attn_b = (const float*)d_in[3];
    const float* cent   = (const float*)d_in[4];
    float* out = (float*)d_out;
    (void)in_sizes; (void)n_in; (void)out_size;

    k_transpose<<<(CC * KK + 255) / 256, 256>>>(conv_w);
    k_assign<<<dim3(NPT, NN), 64>>>(x, attn_w, attn_b);
    k_vlad<<<dim3(CC / CT, NN, NSPLIT), 256>>>(x);
    k_norm1<<<dim3(KK, NN), 256>>>(cent, out);
    k_norm2<<<(NN * KC) / 256, 256>>>(out);
}

// round 8
// speedup vs baseline: 2.1267x; 1.1115x over previous
#include <cuda_runtime.h>
#include <cuda_bf16.h>
#include <math.h>
#include <stdint.h>

// Problem constants
#define NN 48
#define CC 512
#define PP 1600      // 40*40
#define KK 64
#define KC 32768     // K*C
#define NPT 25       // P / 64 tiles (k_assign)
#define NSPLIT 3     // split-P factor for GEMM2

// k_assign chunking
#define ACK 16       // c chunk
#define NCH (CC / ACK)   // 32

// ---------------- scratch ---------------------------------------------------
__device__ float g_w2  [(size_t)NN * PP * KK];   // w2 = softmax*hmp*invn, [n][p][k]
__device__ float g_wsp [NN * NPT * KK];          // partial wsum [n][pt][k]
__device__ float g_convT[CC * KK];               // conv_w transposed [c][k]
__device__ float g_gpart[NN * KK];
__device__ float g_vp  [(size_t)NSPLIT * NN * KK * CC];  // GEMM2 partials

// ---------------- helpers ----------------------------------------------------
__device__ __forceinline__ uint32_t s2u32(const void* p) {
    uint32_t a;
    asm("{ .reg .u64 t; cvta.to.shared.u64 t, %1; cvt.u32.u64 %0, t; }" : "=r"(a) : "l"(p));
    return a;
}
__device__ __forceinline__ void cpa16(uint32_t d, const void* s) {
    asm volatile("cp.async.cg.shared.global [%0], [%1], 16;" :: "r"(d), "l"(s) : "memory");
}
#define CP_COMMIT() asm volatile("cp.async.commit_group;" ::: "memory")
#define CP_WAIT(n)  asm volatile("cp.async.wait_group %0;" :: "n"(n) : "memory")

#define LDSM4(r0,r1,r2,r3,addr) \
    asm volatile("ldmatrix.sync.aligned.m8n8.x4.shared.b16 {%0,%1,%2,%3}, [%4];" \
                 : "=r"(r0), "=r"(r1), "=r"(r2), "=r"(r3) : "r"(addr))
#define LDSM4T(r0,r1,r2,r3,addr) \
    asm volatile("ldmatrix.sync.aligned.m8n8.x4.trans.shared.b16 {%0,%1,%2,%3}, [%4];" \
                 : "=r"(r0), "=r"(r1), "=r"(r2), "=r"(r3) : "r"(addr))
#define MMA(d, a, b0, b1) \
    asm volatile("mma.sync.aligned.m16n8k16.row.col.f32.bf16.bf16.f32 " \
                 "{%0,%1,%2,%3}, {%4,%5,%6,%7}, {%8,%9}, {%0,%1,%2,%3};" \
                 : "+f"((d)[0]), "+f"((d)[1]), "+f"((d)[2]), "+f"((d)[3]) \
                 : "r"((a)[0]), "r"((a)[1]), "r"((a)[2]), "r"((a)[3]), "r"(b0), "r"(b1))

// split fp32 pair into packed bf16 hi (returned) and lo (out param)
__device__ __forceinline__ uint32_t packbf(float a, float b, uint32_t& lo) {
    __nv_bfloat16 ha = __float2bfloat16_rn(a), hb = __float2bfloat16_rn(b);
    float ra = a - __bfloat162float(ha), rb = b - __bfloat162float(hb);
    __nv_bfloat16 la = __float2bfloat16_rn(ra), lb = __float2bfloat16_rn(rb);
    lo = ((uint32_t)__bfloat16_as_ushort(lb) << 16) | (uint32_t)__bfloat16_as_ushort(la);
    return ((uint32_t)__bfloat16_as_ushort(hb) << 16) | (uint32_t)__bfloat16_as_ushort(ha);
}

// ---------------- kernel P: transpose conv_w --------------------------------
__global__ void k_transpose(const float* __restrict__ conv_w) {
    int i = blockIdx.x * 256 + threadIdx.x;
    if (i < CC * KK) {
        int c = i >> 6, k = i & 63;
        g_convT[i] = conv_w[k * CC + c];
    }
}

// ---------------- kernel B: GEMM1 + fused prep + softmax (fp32) -------------
struct AsgG { float cw[2][ACK][64]; float xs[2][ACK][64]; };
struct AsgS { float S[64][65]; float ps[2][64]; };
union AsgU { AsgG g; AsgS s; };

__global__ __launch_bounds__(64, 8) void k_assign(const float* __restrict__ x,
                                                  const float* __restrict__ aw,
                                                  const float* __restrict__ ab) {
    __shared__ __align__(16) AsgU u;
    __shared__ float saw[CC];
    __shared__ float ivb[64], hmb[64];
    int pt = blockIdx.x, n = blockIdx.y;
    int p0 = pt * 64;
    int tid = threadIdx.x;
    int tx = tid & 7, ty = tid >> 3;

    for (int i = tid; i < CC; i += 64) saw[i] = aw[i];

#define ISSUE(ch, b) do {                                                      \
        int _c0 = (ch) * ACK;                                                  \
        _Pragma("unroll")                                                      \
        for (int j = 0; j < 4; j++) {                                          \
            int i = tid + j * 64;                                              \
            int cc = i >> 4, seg = (i & 15) * 4;                               \
            cpa16(s2u32(&u.g.cw[b][cc][seg]), &g_convT[(_c0 + cc) * KK + seg]); \
            cpa16(s2u32(&u.g.xs[b][cc][seg]),                                  \
                  &x[((size_t)(n * CC + _c0 + cc)) * PP + p0 + seg]);          \
        }                                                                      \
    } while (0)

    float acc[2][2][4][4] = {};
    float ss = 0.f, hs = 0.f;

    ISSUE(0, 0); CP_COMMIT();
    for (int ch = 0; ch < NCH; ch++) {
        int b = ch & 1;
        if (ch < NCH - 1) { ISSUE(ch + 1, b ^ 1); CP_COMMIT(); CP_WAIT(1); }
        else CP_WAIT(0);
        __syncthreads();
#pragma unroll 4
        for (int cc = 0; cc < ACK; cc++) {
            float4 a0 = *reinterpret_cast<const float4*>(&u.g.cw[b][cc][ty * 4]);
            float4 a1 = *reinterpret_cast<const float4*>(&u.g.cw[b][cc][32 + ty * 4]);
            float4 b0 = *reinterpret_cast<const float4*>(&u.g.xs[b][cc][tx * 4]);
            float4 b1 = *reinterpret_cast<const float4*>(&u.g.xs[b][cc][32 + tx * 4]);
            float a[2][4] = {{a0.x, a0.y, a0.z, a0.w}, {a1.x, a1.y, a1.z, a1.w}};
            float bb[2][4] = {{b0.x, b0.y, b0.z, b0.w}, {b1.x, b1.y, b1.z, b1.w}};
#pragma unroll
            for (int kh = 0; kh < 2; kh++)
#pragma unroll
                for (int ph = 0; ph < 2; ph++)
#pragma unroll
                    for (int i = 0; i < 4; i++)
#pragma unroll
                        for (int j = 0; j < 4; j++)
                            acc[kh][ph][i][j] += a[kh][i] * bb[ph][j];
            float v = u.g.xs[b][cc][tid];
            ss += v * v;
            hs += fmaxf(v, 0.f) * saw[ch * ACK + cc];
        }
        __syncthreads();
    }

    ivb[tid] = 1.f / fmaxf(sqrtf(ss), 1e-12f);
    hmb[tid] = fmaxf(hs + ab[0], 0.f);
    __syncthreads();

#pragma unroll
    for (int kh = 0; kh < 2; kh++)
#pragma unroll
        for (int ph = 0; ph < 2; ph++)
#pragma unroll
            for (int j = 0; j < 4; j++) {
                int p = ph * 32 + tx * 4 + j;
                float iv = ivb[p];
#pragma unroll
                for (int i = 0; i < 4; i++)
                    u.s.S[p][kh * 32 + ty * 4 + i] = acc[kh][ph][i][j] * iv;
            }
    __syncthreads();

    int lane = tid & 31, wrp = tid >> 5;
    float pa = 0.f, pb = 0.f;
    for (int r8 = 0; r8 < 32; r8++) {
        int r = wrp * 32 + r8;
        float v0 = u.s.S[r][lane];
        float v1 = u.s.S[r][lane + 32];
        float m = fmaxf(v0, v1);
#pragma unroll
        for (int o = 16; o > 0; o >>= 1) m = fmaxf(m, __shfl_xor_sync(0xffffffffu, m, o));
        float e0 = __expf(v0 - m), e1 = __expf(v1 - m);
        float s = e0 + e1;
#pragma unroll
        for (int o = 16; o > 0; o >>= 1) s += __shfl_xor_sync(0xffffffffu, s, o);
        float h  = hmb[r];
        float iv = ivb[r];
        float sc = h / s;
        float w0 = e0 * sc, w1 = e1 * sc;
        size_t base = ((size_t)n * PP + p0 + r) * KK;
        g_w2[base + lane]      = w0 * iv;
        g_w2[base + lane + 32] = w1 * iv;
        pa += w0; pb += w1;
    }
    u.s.ps[wrp][lane]      = pa;
    u.s.ps[wrp][lane + 32] = pb;
    __syncthreads();
    if (tid < 64)
        g_wsp[(n * NPT + pt) * KK + tid] = u.s.ps[0][tid] + u.s.ps[1][tid];
}

// ---------------- kernel C: GEMM2 via mma.sync bf16 split-precision ---------
// CTA: (c-tile 128, n, p-split). D[k=64][c=128] = sum_p w2[k][p] * x[c][p].
// A = w2 (m=k, kdim=p), B = x (n=c, kdim=p) — x's native [c][p] layout IS the
// col-major B. 3 MMA products recover ~fp32 precision.
__global__ __launch_bounds__(128, 4) void k_vlad_mma(const float* __restrict__ x) {
    __shared__ __align__(16) float stgX[2][128][20];            // fp32 x stage
    __shared__ __align__(16) float stgW[2][16][68];             // fp32 w2 stage
    __shared__ __align__(16) __nv_bfloat16 xsH[128][24];        // B hi tiles [c][p]
    __shared__ __align__(16) __nv_bfloat16 xsL[128][24];
    __shared__ __align__(16) __nv_bfloat16 wsH[16][72];         // A^T tiles [p][k]
    __shared__ __align__(16) __nv_bfloat16 wsL[16][72];

    int ct = blockIdx.x, n = blockIdx.y, sp = blockIdx.z;
    int c0 = ct * 128;
    int p0  = (sp == 0) ? 0 : 544 + (sp - 1) * 528;
    int nch = (sp == 0) ? 34 : 33;
    int tid = threadIdx.x;
    int lane = tid & 31, warp = tid >> 5;

    // ldmatrix addresses (fixed over loop)
    int lr = lane & 7, lg = lane >> 3;
    int bRow = warp * 32 + ((lg & 2) ? 8 : 0) + lr;
    int bCol = (lg & 1) ? 8 : 0;
    uint32_t bAH0 = s2u32(&xsH[bRow][bCol]), bAH1 = s2u32(&xsH[bRow + 16][bCol]);
    uint32_t bAL0 = s2u32(&xsL[bRow][bCol]), bAL1 = s2u32(&xsL[bRow + 16][bCol]);
    int aRow = ((lg & 2) ? 8 : 0) + lr;
    int aColB = (lg & 1) ? 8 : 0;
    uint32_t aAH[4], aAL[4];
#pragma unroll
    for (int mt = 0; mt < 4; mt++) {
        aAH[mt] = s2u32(&wsH[aRow][mt * 16 + aColB]);
        aAL[mt] = s2u32(&wsL[aRow][mt * 16 + aColB]);
    }

    const float* xrow = x + ((size_t)(n * CC + c0 + tid)) * PP + p0;
    int wp = tid >> 3, wk = (tid & 7) * 8;
    const float* wrow = g_w2 + ((size_t)n * PP + p0 + wp) * KK + wk;

#define VISSUE(ci, b) do {                                                     \
        const float* _xp = xrow + (ci) * 16;                                   \
        cpa16(s2u32(&stgX[b][tid][0]),  _xp);                                  \
        cpa16(s2u32(&stgX[b][tid][4]),  _xp + 4);                              \
        cpa16(s2u32(&stgX[b][tid][8]),  _xp + 8);                              \
        cpa16(s2u32(&stgX[b][tid][12]), _xp + 12);                             \
        const float* _wp = wrow + (size_t)(ci) * 16 * KK;                      \
        cpa16(s2u32(&stgW[b][wp][wk]),     _wp);                               \
        cpa16(s2u32(&stgW[b][wp][wk + 4]), _wp + 4);                           \
    } while (0)

    float d[4][4][4] = {};

    VISSUE(0, 0); CP_COMMIT();
    for (int i = 0; i < nch; i++) {
        int b = i & 1;
        if (i + 1 < nch) { VISSUE(i + 1, b ^ 1); CP_COMMIT(); CP_WAIT(1); }
        else CP_WAIT(0);
        // convert own staged data (same-thread: no sync needed before this)
        {
            uint32_t hp[8], lp[8];
#pragma unroll
            for (int q = 0; q < 4; q++) {
                float4 v = *reinterpret_cast<float4*>(&stgX[b][tid][q * 4]);
                hp[q * 2]     = packbf(v.x, v.y, lp[q * 2]);
                hp[q * 2 + 1] = packbf(v.z, v.w, lp[q * 2 + 1]);
            }
            *reinterpret_cast<uint4*>(&xsH[tid][0]) = make_uint4(hp[0], hp[1], hp[2], hp[3]);
            *reinterpret_cast<uint4*>(&xsH[tid][8]) = make_uint4(hp[4], hp[5], hp[6], hp[7]);
            *reinterpret_cast<uint4*>(&xsL[tid][0]) = make_uint4(lp[0], lp[1], lp[2], lp[3]);
            *reinterpret_cast<uint4*>(&xsL[tid][8]) = make_uint4(lp[4], lp[5], lp[6], lp[7]);
        }
        {
            uint32_t hp[4], lp[4];
            float4 v0 = *reinterpret_cast<float4*>(&stgW[b][wp][wk]);
            float4 v1 = *reinterpret_cast<float4*>(&stgW[b][wp][wk + 4]);
            hp[0] = packbf(v0.x, v0.y, lp[0]);
            hp[1] = packbf(v0.z, v0.w, lp[1]);
            hp[2] = packbf(v1.x, v1.y, lp[2]);
            hp[3] = packbf(v1.z, v1.w, lp[3]);
            *reinterpret_cast<uint4*>(&wsH[wp][wk]) = make_uint4(hp[0], hp[1], hp[2], hp[3]);
            *reinterpret_cast<uint4*>(&wsL[wp][wk]) = make_uint4(lp[0], lp[1], lp[2], lp[3]);
        }
        __syncthreads();
        // fragments + 48 MMAs
        uint32_t bh[8], bl[8];
        LDSM4(bh[0], bh[1], bh[2], bh[3], bAH0);
        LDSM4(bh[4], bh[5], bh[6], bh[7], bAH1);
        LDSM4(bl[0], bl[1], bl[2], bl[3], bAL0);
        LDSM4(bl[4], bl[5], bl[6], bl[7], bAL1);
#pragma unroll
        for (int mt = 0; mt < 4; mt++) {
            uint32_t ah[4], al[4];
            LDSM4T(ah[0], ah[1], ah[2], ah[3], aAH[mt]);
            LDSM4T(al[0], al[1], al[2], al[3], aAL[mt]);
#pragma unroll
            for (int ng = 0; ng < 4; ng++) {
                uint32_t b0h = bh[ng * 2], b1h = bh[ng * 2 + 1];
                uint32_t b0l = bl[ng * 2], b1l = bl[ng * 2 + 1];
                MMA(d[mt][ng], ah, b0h, b1h);
                MMA(d[mt][ng], ah, b0l, b1l);
                MMA(d[mt][ng], al, b0h, b1h);
            }
        }
        __syncthreads();   // protect tiles before next convert
    }
    // epilogue: write partial tile to g_vp[sp][n][k][c]
    int grp = lane >> 2, q = lane & 3;
#pragma unroll
    for (int mt = 0; mt < 4; mt++)
#pragma unroll
        for (int ng = 0; ng < 4; ng++) {
            int k = mt * 16 + grp;
            int c = c0 + warp * 32 + ng * 8 + q * 2;
            size_t o = (((size_t)sp * NN + n) * KK + k) * CC + c;
            *reinterpret_cast<float2*>(&g_vp[o]) =
                make_float2(d[mt][ng][0], d[mt][ng][1]);
            *reinterpret_cast<float2*>(&g_vp[o + 8 * CC]) =
                make_float2(d[mt][ng][2], d[mt][ng][3]);
        }
}

// ---------------- kernel E: reduce partials + residual + intra L2 ----------
__global__ __launch_bounds__(256) void k_norm1(const float* __restrict__ cent,
                                               float* __restrict__ out) {
    __shared__ float red[256];
    int k = blockIdx.x, n = blockIdx.y, tid = threadIdx.x;
    float wsum = 0.f;
#pragma unroll
    for (int t = 0; t < NPT; t++) wsum += g_wsp[(n * NPT + t) * KK + k];

    float t1a = 0.f, t1b = 0.f;
#pragma unroll
    for (int s = 0; s < NSPLIT; s++) {
        size_t b = (((size_t)s * NN + n) * KK + k) * CC;
        t1a += g_vp[b + tid];
        t1b += g_vp[b + tid + 256];
    }
    size_t base = (size_t)n * KC + (size_t)k * CC;
    float v1 = t1a - wsum * cent[k * CC + tid];
    float v2 = t1b - wsum * cent[k * CC + tid + 256];
    red[tid] = v1 * v1 + v2 * v2;
    __syncthreads();
    for (int o = 128; o > 0; o >>= 1) {
        if (tid < o) red[tid] += red[tid + o];
        __syncthreads();
    }
    float tot = red[0];
    float inv = 1.f / fmaxf(sqrtf(tot), 1e-12f);
    out[base + tid]       = v1 * inv;
    out[base + tid + 256] = v2 * inv;
    if (tid == 0) g_gpart[n * KK + k] = tot * inv * inv;
}

// ---------------- kernel F: global L2 normalize ------------------------------
__global__ __launch_bounds__(256) void k_norm2(float* __restrict__ out) {
    __shared__ float s[KK];
    __shared__ float ginv;
    size_t i = (size_t)blockIdx.x * 256 + threadIdx.x;
    int n = (int)(i >> 15);
    if (threadIdx.x < KK) s[threadIdx.x] = g_gpart[n * KK + threadIdx.x];
    __syncthreads();
    if (threadIdx.x == 0) {
        float t = 0.f;
#pragma unroll
        for (int j = 0; j < KK; j++) t += s[j];
        ginv = 1.f / fmaxf(sqrtf(t), 1e-12f);
    }
    __syncthreads();
    out[i] *= ginv;
}

// ---------------- launch -----------------------------------------------------
extern "C" void kernel_launch(void* const* d_in, const int* in_sizes, int n_in,
                              void* d_out, int out_size) {
    const float* x      = (const float*)d_in[0];
    const float* conv_w = (const float*)d_in[1];
    const float* attn_w = (const float*)d_in[2];
    const float* attn_b = (const float*)d_in[3];
    const float* cent   = (const float*)d_in[4];
    float* out = (float*)d_out;
    (void)in_sizes; (void)n_in; (void)out_size;

    k_transpose<<<(CC * KK + 255) / 256, 256>>>(conv_w);
    k_assign<<<dim3(NPT, NN), 64>>>(x, attn_w, attn_b);
    k_vlad_mma<<<dim3(4, NN, NSPLIT), 128>>>(x);
    k_norm1<<<dim3(KK, NN), 256>>>(cent, out);
    k_norm2<<<(NN * KC) / 256, 256>>>(out);
}

// round 9
// speedup vs baseline: 2.5877x; 1.2168x over previous
#include <cuda_runtime.h>
#include <cuda_bf16.h>
#include <math.h>
#include <stdint.h>

// Problem constants
#define NN 48
#define CC 512
#define PP 1600      // 40*40
#define KK 64
#define KC 32768     // K*C
#define NPT 25       // P / 64 tiles (k_assign)
#define NSPLIT 3     // split-P factor for GEMM2

// ---------------- scratch ---------------------------------------------------
__device__ float g_w2  [(size_t)NN * PP * KK];   // w2 = softmax*hmp*invn, [n][p][k]
__device__ float g_wsp [NN * NPT * KK];          // partial wsum [n][pt][k]
__device__ __nv_bfloat16 g_cwH[CC * KK];         // conv_w^T bf16 hi [c][k]
__device__ __nv_bfloat16 g_cwL[CC * KK];         // conv_w^T bf16 lo residual
__device__ float g_gpart[NN * KK];
__device__ float g_vp  [(size_t)NSPLIT * NN * KK * CC];  // GEMM2 partials

// ---------------- helpers ----------------------------------------------------
__device__ __forceinline__ uint32_t s2u32(const void* p) {
    uint32_t a;
    asm("{ .reg .u64 t; cvta.to.shared.u64 t, %1; cvt.u32.u64 %0, t; }" : "=r"(a) : "l"(p));
    return a;
}
__device__ __forceinline__ void cpa16(uint32_t d, const void* s) {
    asm volatile("cp.async.cg.shared.global [%0], [%1], 16;" :: "r"(d), "l"(s) : "memory");
}
#define CP_COMMIT() asm volatile("cp.async.commit_group;" ::: "memory")
#define CP_WAIT(n)  asm volatile("cp.async.wait_group %0;" :: "n"(n) : "memory")

#define LDSM4(r0,r1,r2,r3,addr) \
    asm volatile("ldmatrix.sync.aligned.m8n8.x4.shared.b16 {%0,%1,%2,%3}, [%4];" \
                 : "=r"(r0), "=r"(r1), "=r"(r2), "=r"(r3) : "r"(addr))
#define LDSM4T(r0,r1,r2,r3,addr) \
    asm volatile("ldmatrix.sync.aligned.m8n8.x4.trans.shared.b16 {%0,%1,%2,%3}, [%4];" \
                 : "=r"(r0), "=r"(r1), "=r"(r2), "=r"(r3) : "r"(addr))
#define MMA(d, a, b0, b1) \
    asm volatile("mma.sync.aligned.m16n8k16.row.col.f32.bf16.bf16.f32 " \
                 "{%0,%1,%2,%3}, {%4,%5,%6,%7}, {%8,%9}, {%0,%1,%2,%3};" \
                 : "+f"((d)[0]), "+f"((d)[1]), "+f"((d)[2]), "+f"((d)[3]) \
                 : "r"((a)[0]), "r"((a)[1]), "r"((a)[2]), "r"((a)[3]), "r"(b0), "r"(b1))

// split fp32 pair into packed bf16 hi (returned) and lo (out param)
__device__ __forceinline__ uint32_t packbf(float a, float b, uint32_t& lo) {
    __nv_bfloat16 ha = __float2bfloat16_rn(a), hb = __float2bfloat16_rn(b);
    float ra = a - __bfloat162float(ha), rb = b - __bfloat162float(hb);
    __nv_bfloat16 la = __float2bfloat16_rn(ra), lb = __float2bfloat16_rn(rb);
    lo = ((uint32_t)__bfloat16_as_ushort(lb) << 16) | (uint32_t)__bfloat16_as_ushort(la);
    return ((uint32_t)__bfloat16_as_ushort(hb) << 16) | (uint32_t)__bfloat16_as_ushort(ha);
}

// ---------------- kernel P: transpose + bf16-split conv_w -------------------
__global__ void k_transpose(const float* __restrict__ conv_w) {
    int i = blockIdx.x * 256 + threadIdx.x;   // i = c*64 + k
    if (i < CC * KK) {
        int c = i >> 6, k = i & 63;
        float v = conv_w[k * CC + c];
        __nv_bfloat16 h = __float2bfloat16_rn(v);
        g_cwH[i] = h;
        g_cwL[i] = __float2bfloat16_rn(v - __bfloat162float(h));
    }
}

// ---------------- kernel B: GEMM1 via mma.sync bf16 + prep + softmax --------
// CTA: 128 thr, tile [k=64][p=64], kdim = C = 512 in 32 chunks of 16.
// A = conv_w [k][c] stored [c][k] bf16 (pre-split), LDSM4T.
// B = x chunk [c16][p64] = [kdim][n], LDSM4T.
struct AsgG {
    float stgX[2][16][68];               // fp32 x stage
    __nv_bfloat16 awH[2][16][72];        // conv hi tiles [c][k]
    __nv_bfloat16 awL[2][16][72];
    __nv_bfloat16 xsH[16][72];           // x hi tiles [c][p]
    __nv_bfloat16 xsL[16][72];
};
struct AsgS {
    float S[64][65];                      // raw logits [p][k]
    float ps[4][64];                      // warp wsum partials
    float r1[2][64];                      // ss partials
    float r2[2][64];                      // hs partials
};
union AsgU { AsgG g; AsgS s; };

__global__ __launch_bounds__(128, 8) void k_assign_mma(const float* __restrict__ x,
                                                       const float* __restrict__ aw,
                                                       const float* __restrict__ ab) {
    __shared__ __align__(16) AsgU u;
    __shared__ float saw[CC];
    __shared__ float ivb[64], hmb[64];
    int pt = blockIdx.x, n = blockIdx.y;
    int p0 = pt * 64;
    int tid = threadIdx.x;
    int lane = tid & 31, warp = tid >> 5;

    for (int i = tid; i < CC; i += 128) saw[i] = aw[i];

    // ldmatrix lane addressing
    int lr = lane & 7, lg = lane >> 3;
    // A (from [kdim][m] tiles, trans): r0=(k0-7,m0-7) r1=(k0-7,m8-15) r2=(k8-15,m0-7) r3=(k8-15,m8-15)
    int aRow = ((lg & 2) ? 8 : 0) + lr, aCol = (lg & 1) ? 8 : 0;
    // B (from [kdim][n] tiles, trans): r0=(k0-7,n0-7) r1=(k8-15,n0-7) r2=(k0-7,n8-15) r3=(k8-15,n8-15)
    int bRow = ((lg & 1) ? 8 : 0) + lr, bCol = warp * 16 + ((lg & 2) ? 8 : 0);
    uint32_t bH = s2u32(&u.g.xsH[bRow][bCol]);
    uint32_t bL = s2u32(&u.g.xsL[bRow][bCol]);

    // staging mapping: thread -> (row cc, 8 cols at seg)
    int cc = tid >> 3, seg = (tid & 7) * 8;
    const float* xsrc = x + ((size_t)(n * CC) + cc) * PP + p0 + seg;

#define AISSUE(ch, b) do {                                                     \
        int _c0 = (ch) * 16;                                                   \
        cpa16(s2u32(&u.g.stgX[b][cc][seg]),     xsrc + (size_t)_c0 * PP);      \
        cpa16(s2u32(&u.g.stgX[b][cc][seg + 4]), xsrc + (size_t)_c0 * PP + 4);  \
        cpa16(s2u32(&u.g.awH[b][cc][seg]), g_cwH + (_c0 + cc) * KK + seg);     \
        cpa16(s2u32(&u.g.awL[b][cc][seg]), g_cwL + (_c0 + cc) * KK + seg);     \
    } while (0)

    float d[4][2][4] = {};
    float ss = 0.f, hs = 0.f;
    int pcol = tid & 63, rb = (tid >> 6) * 8;

    AISSUE(0, 0); CP_COMMIT();
    for (int ch = 0; ch < 32; ch++) {
        int b = ch & 1;
        if (ch < 31) { AISSUE(ch + 1, b ^ 1); CP_COMMIT(); CP_WAIT(1); }
        else CP_WAIT(0);
        // convert OWN staged x row-segment to bf16 hi/lo (no sync needed)
        {
            uint32_t hp[4], lp[4];
            float4 v0 = *reinterpret_cast<float4*>(&u.g.stgX[b][cc][seg]);
            float4 v1 = *reinterpret_cast<float4*>(&u.g.stgX[b][cc][seg + 4]);
            hp[0] = packbf(v0.x, v0.y, lp[0]);
            hp[1] = packbf(v0.z, v0.w, lp[1]);
            hp[2] = packbf(v1.x, v1.y, lp[2]);
            hp[3] = packbf(v1.z, v1.w, lp[3]);
            *reinterpret_cast<uint4*>(&u.g.xsH[cc][seg]) = make_uint4(hp[0], hp[1], hp[2], hp[3]);
            *reinterpret_cast<uint4*>(&u.g.xsL[cc][seg]) = make_uint4(lp[0], lp[1], lp[2], lp[3]);
        }
        __syncthreads();
        // prep reductions from fp32 stage (column-wise; stage live this iter)
#pragma unroll
        for (int r = 0; r < 8; r++) {
            float v = u.g.stgX[b][rb + r][pcol];
            ss += v * v;
            hs += fmaxf(v, 0.f) * saw[ch * 16 + rb + r];
        }
        // B fragments (both n8 tiles of this warp's n16)
        uint32_t bh[4], bl[4];
        LDSM4T(bh[0], bh[1], bh[2], bh[3], bH);
        LDSM4T(bl[0], bl[1], bl[2], bl[3], bL);
        uint32_t aH0 = s2u32(&u.g.awH[b][aRow][aCol]);
        uint32_t aL0 = s2u32(&u.g.awL[b][aRow][aCol]);
#pragma unroll
        for (int mt = 0; mt < 4; mt++) {
            uint32_t ah[4], al[4];
            LDSM4T(ah[0], ah[1], ah[2], ah[3], aH0 + mt * 32);
            LDSM4T(al[0], al[1], al[2], al[3], aL0 + mt * 32);
            MMA(d[mt][0], ah, bh[0], bh[1]);
            MMA(d[mt][0], ah, bl[0], bl[1]);
            MMA(d[mt][0], al, bh[0], bh[1]);
            MMA(d[mt][1], ah, bh[2], bh[3]);
            MMA(d[mt][1], ah, bl[2], bl[3]);
            MMA(d[mt][1], al, bh[2], bh[3]);
        }
        __syncthreads();
    }

    // write raw logits S[p][k] from fragments + prep partials
    int grp = lane >> 2, q = lane & 3;
#pragma unroll
    for (int mt = 0; mt < 4; mt++)
#pragma unroll
        for (int ng = 0; ng < 2; ng++) {
            int p = warp * 16 + ng * 8 + q * 2;
            int k = mt * 16 + grp;
            u.s.S[p][k]         = d[mt][ng][0];
            u.s.S[p + 1][k]     = d[mt][ng][1];
            u.s.S[p][k + 8]     = d[mt][ng][2];
            u.s.S[p + 1][k + 8] = d[mt][ng][3];
        }
    u.s.r1[tid >> 6][tid & 63] = ss;
    u.s.r2[tid >> 6][tid & 63] = hs;
    __syncthreads();
    if (tid < 64) {
        float st = u.s.r1[0][tid] + u.s.r1[1][tid];
        float ht = u.s.r2[0][tid] + u.s.r2[1][tid];
        ivb[tid] = 1.f / fmaxf(sqrtf(st), 1e-12f);
        hmb[tid] = fmaxf(ht + ab[0], 0.f);
    }
    __syncthreads();

    // softmax over k per p-row; 4 warps x 16 rows
    float pa = 0.f, pb = 0.f;
    for (int r8 = 0; r8 < 16; r8++) {
        int r = warp * 16 + r8;
        float iv = ivb[r];
        float v0 = u.s.S[r][lane] * iv;
        float v1 = u.s.S[r][lane + 32] * iv;
        float m = fmaxf(v0, v1);
#pragma unroll
        for (int o = 16; o > 0; o >>= 1) m = fmaxf(m, __shfl_xor_sync(0xffffffffu, m, o));
        float e0 = __expf(v0 - m), e1 = __expf(v1 - m);
        float s = e0 + e1;
#pragma unroll
        for (int o = 16; o > 0; o >>= 1) s += __shfl_xor_sync(0xffffffffu, s, o);
        float h = hmb[r];
        float sc = h / s;
        float w0 = e0 * sc, w1 = e1 * sc;
        size_t base = ((size_t)n * PP + p0 + r) * KK;
        g_w2[base + lane]      = w0 * iv;
        g_w2[base + lane + 32] = w1 * iv;
        pa += w0; pb += w1;
    }
    u.s.ps[warp][lane]      = pa;
    u.s.ps[warp][lane + 32] = pb;
    __syncthreads();
    if (tid < 64)
        g_wsp[(n * NPT + pt) * KK + tid] =
            u.s.ps[0][tid] + u.s.ps[1][tid] + u.s.ps[2][tid] + u.s.ps[3][tid];
}

// ---------------- kernel C: GEMM2 via mma.sync bf16 split-precision ---------
__global__ __launch_bounds__(128, 4) void k_vlad_mma(const float* __restrict__ x) {
    __shared__ __align__(16) float stgX[2][128][20];
    __shared__ __align__(16) float stgW[2][16][68];
    __shared__ __align__(16) __nv_bfloat16 xsH[128][24];
    __shared__ __align__(16) __nv_bfloat16 xsL[128][24];
    __shared__ __align__(16) __nv_bfloat16 wsH[16][72];
    __shared__ __align__(16) __nv_bfloat16 wsL[16][72];

    int ct = blockIdx.x, n = blockIdx.y, sp = blockIdx.z;
    int c0 = ct * 128;
    int p0  = (sp == 0) ? 0 : 544 + (sp - 1) * 528;
    int nch = (sp == 0) ? 34 : 33;
    int tid = threadIdx.x;
    int lane = tid & 31, warp = tid >> 5;

    int lr = lane & 7, lg = lane >> 3;
    int bRow = warp * 32 + ((lg & 2) ? 8 : 0) + lr;
    int bCol = (lg & 1) ? 8 : 0;
    uint32_t bAH0 = s2u32(&xsH[bRow][bCol]), bAH1 = s2u32(&xsH[bRow + 16][bCol]);
    uint32_t bAL0 = s2u32(&xsL[bRow][bCol]), bAL1 = s2u32(&xsL[bRow + 16][bCol]);
    int aRow = ((lg & 2) ? 8 : 0) + lr;
    int aColB = (lg & 1) ? 8 : 0;
    uint32_t aAH[4], aAL[4];
#pragma unroll
    for (int mt = 0; mt < 4; mt++) {
        aAH[mt] = s2u32(&wsH[aRow][mt * 16 + aColB]);
        aAL[mt] = s2u32(&wsL[aRow][mt * 16 + aColB]);
    }

    const float* xrow = x + ((size_t)(n * CC + c0 + tid)) * PP + p0;
    int wp = tid >> 3, wk = (tid & 7) * 8;
    const float* wrow = g_w2 + ((size_t)n * PP + p0 + wp) * KK + wk;

#define VISSUE(ci, b) do {                                                     \
        const float* _xp = xrow + (ci) * 16;                                   \
        cpa16(s2u32(&stgX[b][tid][0]),  _xp);                                  \
        cpa16(s2u32(&stgX[b][tid][4]),  _xp + 4);                              \
        cpa16(s2u32(&stgX[b][tid][8]),  _xp + 8);                              \
        cpa16(s2u32(&stgX[b][tid][12]), _xp + 12);                             \
        const float* _wp = wrow + (size_t)(ci) * 16 * KK;                      \
        cpa16(s2u32(&stgW[b][wp][wk]),     _wp);                               \
        cpa16(s2u32(&stgW[b][wp][wk + 4]), _wp + 4);                           \
    } while (0)

    float d[4][4][4] = {};

    VISSUE(0, 0); CP_COMMIT();
    for (int i = 0; i < nch; i++) {
        int b = i & 1;
        if (i + 1 < nch) { VISSUE(i + 1, b ^ 1); CP_COMMIT(); CP_WAIT(1); }
        else CP_WAIT(0);
        {
            uint32_t hp[8], lp[8];
#pragma unroll
            for (int q = 0; q < 4; q++) {
                float4 v = *reinterpret_cast<float4*>(&stgX[b][tid][q * 4]);
                hp[q * 2]     = packbf(v.x, v.y, lp[q * 2]);
                hp[q * 2 + 1] = packbf(v.z, v.w, lp[q * 2 + 1]);
            }
            *reinterpret_cast<uint4*>(&xsH[tid][0]) = make_uint4(hp[0], hp[1], hp[2], hp[3]);
            *reinterpret_cast<uint4*>(&xsH[tid][8]) = make_uint4(hp[4], hp[5], hp[6], hp[7]);
            *reinterpret_cast<uint4*>(&xsL[tid][0]) = make_uint4(lp[0], lp[1], lp[2], lp[3]);
            *reinterpret_cast<uint4*>(&xsL[tid][8]) = make_uint4(lp[4], lp[5], lp[6], lp[7]);
        }
        {
            uint32_t hp[4], lp[4];
            float4 v0 = *reinterpret_cast<float4*>(&stgW[b][wp][wk]);
            float4 v1 = *reinterpret_cast<float4*>(&stgW[b][wp][wk + 4]);
            hp[0] = packbf(v0.x, v0.y, lp[0]);
            hp[1] = packbf(v0.z, v0.w, lp[1]);
            hp[2] = packbf(v1.x, v1.y, lp[2]);
            hp[3] = packbf(v1.z, v1.w, lp[3]);
            *reinterpret_cast<uint4*>(&wsH[wp][wk]) = make_uint4(hp[0], hp[1], hp[2], hp[3]);
            *reinterpret_cast<uint4*>(&wsL[wp][wk]) = make_uint4(lp[0], lp[1], lp[2], lp[3]);
        }
        __syncthreads();
        uint32_t bh[8], bl[8];
        LDSM4(bh[0], bh[1], bh[2], bh[3], bAH0);
        LDSM4(bh[4], bh[5], bh[6], bh[7], bAH1);
        LDSM4(bl[0], bl[1], bl[2], bl[3], bAL0);
        LDSM4(bl[4], bl[5], bl[6], bl[7], bAL1);
#pragma unroll
        for (int mt = 0; mt < 4; mt++) {
            uint32_t ah[4], al[4];
            LDSM4T(ah[0], ah[1], ah[2], ah[3], aAH[mt]);
            LDSM4T(al[0], al[1], al[2], al[3], aAL[mt]);
#pragma unroll
            for (int ng = 0; ng < 4; ng++) {
                uint32_t b0h = bh[ng * 2], b1h = bh[ng * 2 + 1];
                uint32_t b0l = bl[ng * 2], b1l = bl[ng * 2 + 1];
                MMA(d[mt][ng], ah, b0h, b1h);
                MMA(d[mt][ng], ah, b0l, b1l);
                MMA(d[mt][ng], al, b0h, b1h);
            }
        }
        __syncthreads();
    }
    int grp = lane >> 2, q = lane & 3;
#pragma unroll
    for (int mt = 0; mt < 4; mt++)
#pragma unroll
        for (int ng = 0; ng < 4; ng++) {
            int k = mt * 16 + grp;
            int c = c0 + warp * 32 + ng * 8 + q * 2;
            size_t o = (((size_t)sp * NN + n) * KK + k) * CC + c;
            *reinterpret_cast<float2*>(&g_vp[o]) =
                make_float2(d[mt][ng][0], d[mt][ng][1]);
            *reinterpret_cast<float2*>(&g_vp[o + 8 * CC]) =
                make_float2(d[mt][ng][2], d[mt][ng][3]);
        }
}

// ---------------- kernel E: reduce partials + residual + intra L2 ----------
__global__ __launch_bounds__(256) void k_norm1(const float* __restrict__ cent,
                                               float* __restrict__ out) {
    __shared__ float red[256];
    int k = blockIdx.x, n = blockIdx.y, tid = threadIdx.x;
    float wsum = 0.f;
#pragma unroll
    for (int t = 0; t < NPT; t++) wsum += g_wsp[(n * NPT + t) * KK + k];

    float t1a = 0.f, t1b = 0.f;
#pragma unroll
    for (int s = 0; s < NSPLIT; s++) {
        size_t b = (((size_t)s * NN + n) * KK + k) * CC;
        t1a += g_vp[b + tid];
        t1b += g_vp[b + tid + 256];
    }
    size_t base = (size_t)n * KC + (size_t)k * CC;
    float v1 = t1a - wsum * cent[k * CC + tid];
    float v2 = t1b - wsum * cent[k * CC + tid + 256];
    red[tid] = v1 * v1 + v2 * v2;
    __syncthreads();
    for (int o = 128; o > 0; o >>= 1) {
        if (tid < o) red[tid] += red[tid + o];
        __syncthreads();
    }
    float tot = red[0];
    float inv = 1.f / fmaxf(sqrtf(tot), 1e-12f);
    out[base + tid]       = v1 * inv;
    out[base + tid + 256] = v2 * inv;
    if (tid == 0) g_gpart[n * KK + k] = tot * inv * inv;
}

// ---------------- kernel F: global L2 normalize ------------------------------
__global__ __launch_bounds__(256) void k_norm2(float* __restrict__ out) {
    __shared__ float s[KK];
    __shared__ float ginv;
    size_t i = (size_t)blockIdx.x * 256 + threadIdx.x;
    int n = (int)(i >> 15);
    if (threadIdx.x < KK) s[threadIdx.x] = g_gpart[n * KK + threadIdx.x];
    __syncthreads();
    if (threadIdx.x == 0) {
        float t = 0.f;
#pragma unroll
        for (int j = 0; j < KK; j++) t += s[j];
        ginv = 1.f / fmaxf(sqrtf(t), 1e-12f);
    }
    __syncthreads();
    out[i] *= ginv;
}

// ---------------- launch -----------------------------------------------------
extern "C" void kernel_launch(void* const* d_in, const int* in_sizes, int n_in,
                              void* d_out, int out_size) {
    const float* x      = (const float*)d_in[0];
    const float* conv_w = (const float*)d_in[1];
    const float* attn_w = (const float*)d_in[2];
    const float* attn_b = (const float*)d_in[3];
    const float* cent   = (const float*)d_in[4];
    float* out = (float*)d_out;
    (void)in_sizes; (void)n_in; (void)out_size;

    k_transpose<<<(CC * KK + 255) / 256, 256>>>(conv_w);
    k_assign_mma<<<dim3(NPT, NN), 128>>>(x, attn_w, attn_b);
    k_vlad_mma<<<dim3(4, NN, NSPLIT), 128>>>(x);
    k_norm1<<<dim3(KK, NN), 256>>>(cent, out);
    k_norm2<<<(NN * KC) / 256, 256>>>(out);
}

// round 10
// speedup vs baseline: 2.9307x; 1.1326x over previous
#include <cuda_runtime.h>
#include <cuda_fp16.h>
#include <math.h>
#include <stdint.h>

// Problem constants
#define NN 48
#define CC 512
#define PP 1600      // 40*40
#define KK 64
#define KC 32768     // K*C
#define NPT 25       // P / 64 tiles (k_assign)
#define NSPLIT 3     // split-P factor for GEMM2

// ---------------- scratch ---------------------------------------------------
__device__ __align__(256) __half g_w2h[(size_t)NN * PP * KK];  // w2 fp16 hi [n][p][k]
__device__ __align__(256) __half g_w2l[(size_t)NN * PP * KK];  // w2 fp16 lo residual
__device__ float g_wsp [NN * NPT * KK];          // partial wsum [n][pt][k]
__device__ __align__(256) __half g_cwH[CC * KK]; // conv_w^T fp16 hi [c][k]
__device__ __align__(256) __half g_cwL[CC * KK]; // conv_w^T fp16 lo residual
__device__ float g_gpart[NN * KK];
__device__ float g_vp  [(size_t)NSPLIT * NN * KK * CC];  // GEMM2 partials

// ---------------- helpers ----------------------------------------------------
__device__ __forceinline__ uint32_t s2u32(const void* p) {
    uint32_t a;
    asm("{ .reg .u64 t; cvta.to.shared.u64 t, %1; cvt.u32.u64 %0, t; }" : "=r"(a) : "l"(p));
    return a;
}
__device__ __forceinline__ void cpa16(uint32_t d, const void* s) {
    asm volatile("cp.async.cg.shared.global [%0], [%1], 16;" :: "r"(d), "l"(s) : "memory");
}
#define CP_COMMIT() asm volatile("cp.async.commit_group;" ::: "memory")
#define CP_WAIT(n)  asm volatile("cp.async.wait_group %0;" :: "n"(n) : "memory")

#define LDSM4(r0,r1,r2,r3,addr) \
    asm volatile("ldmatrix.sync.aligned.m8n8.x4.shared.b16 {%0,%1,%2,%3}, [%4];" \
                 : "=r"(r0), "=r"(r1), "=r"(r2), "=r"(r3) : "r"(addr))
#define LDSM4T(r0,r1,r2,r3,addr) \
    asm volatile("ldmatrix.sync.aligned.m8n8.x4.trans.shared.b16 {%0,%1,%2,%3}, [%4];" \
                 : "=r"(r0), "=r"(r1), "=r"(r2), "=r"(r3) : "r"(addr))
#define MMAH(d, a, b0, b1) \
    asm volatile("mma.sync.aligned.m16n8k16.row.col.f32.f16.f16.f32 " \
                 "{%0,%1,%2,%3}, {%4,%5,%6,%7}, {%8,%9}, {%0,%1,%2,%3};" \
                 : "+f"((d)[0]), "+f"((d)[1]), "+f"((d)[2]), "+f"((d)[3]) \
                 : "r"((a)[0]), "r"((a)[1]), "r"((a)[2]), "r"((a)[3]), "r"(b0), "r"(b1))

__device__ __forceinline__ uint32_t packh(float a, float b) {
    __half2 h = __floats2half2_rn(a, b);
    return *reinterpret_cast<uint32_t*>(&h);
}

// ---------------- kernel P: transpose + fp16-split conv_w -------------------
__global__ void k_transpose(const float* __restrict__ conv_w) {
    int i = blockIdx.x * 256 + threadIdx.x;   // i = c*64 + k
    if (i < CC * KK) {
        int c = i >> 6, k = i & 63;
        float v = conv_w[k * CC + c];
        __half h = __float2half_rn(v);
        g_cwH[i] = h;
        g_cwL[i] = __float2half_rn(v - __half2float(h));
    }
}

// ---------------- kernel B: GEMM1 via fp16 mma (2-product) + prep + softmax -
// CTA: 128 thr, tile [k=64][p=64], kdim = C = 512 in 32 chunks of 16.
// A = conv_w [c][k] fp16 hi/lo (pre-split), LDSM4T. B = x chunk fp16 single.
struct AsgG {
    float stgX[2][16][68];               // fp32 x stage
    __half awH[2][16][72];               // conv hi tiles [c][k]
    __half awL[2][16][72];
    __half xsF[16][72];                  // x fp16 tiles [c][p]
};
struct AsgS {
    float S[64][65];                      // raw logits [p][k]
    float ps[4][64];                      // warp wsum partials
    float r1[2][64];                      // ss partials
    float r2[2][64];                      // hs partials
};
union AsgU { AsgG g; AsgS s; };

__global__ __launch_bounds__(128, 8) void k_assign_mma(const float* __restrict__ x,
                                                       const float* __restrict__ aw,
                                                       const float* __restrict__ ab) {
    __shared__ __align__(16) AsgU u;
    __shared__ float saw[CC];
    __shared__ float ivb[64], hmb[64];
    int pt = blockIdx.x, n = blockIdx.y;
    int p0 = pt * 64;
    int tid = threadIdx.x;
    int lane = tid & 31, warp = tid >> 5;

    for (int i = tid; i < CC; i += 128) saw[i] = aw[i];

    // ldmatrix lane addressing
    int lr = lane & 7, lg = lane >> 3;
    int aRow = ((lg & 2) ? 8 : 0) + lr, aCol = (lg & 1) ? 8 : 0;
    int bRow = ((lg & 1) ? 8 : 0) + lr, bCol = warp * 16 + ((lg & 2) ? 8 : 0);
    uint32_t bF = s2u32(&u.g.xsF[bRow][bCol]);

    // staging mapping: thread -> (row cc, 8 cols at seg)
    int cc = tid >> 3, seg = (tid & 7) * 8;
    const float* xsrc = x + ((size_t)(n * CC) + cc) * PP + p0 + seg;

#define AISSUE(ch, b) do {                                                     \
        int _c0 = (ch) * 16;                                                   \
        cpa16(s2u32(&u.g.stgX[b][cc][seg]),     xsrc + (size_t)_c0 * PP);      \
        cpa16(s2u32(&u.g.stgX[b][cc][seg + 4]), xsrc + (size_t)_c0 * PP + 4);  \
        cpa16(s2u32(&u.g.awH[b][cc][seg]), g_cwH + (_c0 + cc) * KK + seg);     \
        cpa16(s2u32(&u.g.awL[b][cc][seg]), g_cwL + (_c0 + cc) * KK + seg);     \
    } while (0)

    float d[4][2][4] = {};
    float ss = 0.f, hs = 0.f;
    int pcol = tid & 63, rb = (tid >> 6) * 8;

    AISSUE(0, 0); CP_COMMIT();
    for (int ch = 0; ch < 32; ch++) {
        int b = ch & 1;
        if (ch < 31) { AISSUE(ch + 1, b ^ 1); CP_COMMIT(); CP_WAIT(1); }
        else CP_WAIT(0);
        // convert OWN staged x row-segment to single fp16
        {
            float4 v0 = *reinterpret_cast<float4*>(&u.g.stgX[b][cc][seg]);
            float4 v1 = *reinterpret_cast<float4*>(&u.g.stgX[b][cc][seg + 4]);
            uint4 hv = make_uint4(packh(v0.x, v0.y), packh(v0.z, v0.w),
                                  packh(v1.x, v1.y), packh(v1.z, v1.w));
            *reinterpret_cast<uint4*>(&u.g.xsF[cc][seg]) = hv;
        }
        __syncthreads();
        // prep reductions from fp32 stage (stage live this iter)
#pragma unroll
        for (int r = 0; r < 8; r++) {
            float v = u.g.stgX[b][rb + r][pcol];
            ss += v * v;
            hs += fmaxf(v, 0.f) * saw[ch * 16 + rb + r];
        }
        // B fragments (single fp16)
        uint32_t bf[4];
        LDSM4T(bf[0], bf[1], bf[2], bf[3], bF);
        uint32_t aH0 = s2u32(&u.g.awH[b][aRow][aCol]);
        uint32_t aL0 = s2u32(&u.g.awL[b][aRow][aCol]);
#pragma unroll
        for (int mt = 0; mt < 4; mt++) {
            uint32_t ah[4], al[4];
            LDSM4T(ah[0], ah[1], ah[2], ah[3], aH0 + mt * 32);
            LDSM4T(al[0], al[1], al[2], al[3], aL0 + mt * 32);
            MMAH(d[mt][0], ah, bf[0], bf[1]);
            MMAH(d[mt][0], al, bf[0], bf[1]);
            MMAH(d[mt][1], ah, bf[2], bf[3]);
            MMAH(d[mt][1], al, bf[2], bf[3]);
        }
        __syncthreads();
    }

    // write raw logits S[p][k] from fragments + prep partials
    int grp = lane >> 2, q = lane & 3;
#pragma unroll
    for (int mt = 0; mt < 4; mt++)
#pragma unroll
        for (int ng = 0; ng < 2; ng++) {
            int p = warp * 16 + ng * 8 + q * 2;
            int k = mt * 16 + grp;
            u.s.S[p][k]         = d[mt][ng][0];
            u.s.S[p + 1][k]     = d[mt][ng][1];
            u.s.S[p][k + 8]     = d[mt][ng][2];
            u.s.S[p + 1][k + 8] = d[mt][ng][3];
        }
    u.s.r1[tid >> 6][tid & 63] = ss;
    u.s.r2[tid >> 6][tid & 63] = hs;
    __syncthreads();
    if (tid < 64) {
        float st = u.s.r1[0][tid] + u.s.r1[1][tid];
        float ht = u.s.r2[0][tid] + u.s.r2[1][tid];
        ivb[tid] = 1.f / fmaxf(sqrtf(st), 1e-12f);
        hmb[tid] = fmaxf(ht + ab[0], 0.f);
    }
    __syncthreads();

    // softmax over k per p-row; 4 warps x 16 rows. w2 stored fp16 hi/lo.
    float pa = 0.f, pb = 0.f;
    for (int r8 = 0; r8 < 16; r8++) {
        int r = warp * 16 + r8;
        float iv = ivb[r];
        float v0 = u.s.S[r][lane] * iv;
        float v1 = u.s.S[r][lane + 32] * iv;
        float m = fmaxf(v0, v1);
#pragma unroll
        for (int o = 16; o > 0; o >>= 1) m = fmaxf(m, __shfl_xor_sync(0xffffffffu, m, o));
        float e0 = __expf(v0 - m), e1 = __expf(v1 - m);
        float s = e0 + e1;
#pragma unroll
        for (int o = 16; o > 0; o >>= 1) s += __shfl_xor_sync(0xffffffffu, s, o);
        float h = hmb[r];
        float sc = h / s;
        float w0 = e0 * sc, w1 = e1 * sc;
        float w20 = w0 * iv, w21 = w1 * iv;
        __half h0 = __float2half_rn(w20);
        __half h1 = __float2half_rn(w21);
        size_t base = ((size_t)n * PP + p0 + r) * KK;
        g_w2h[base + lane]      = h0;
        g_w2h[base + lane + 32] = h1;
        g_w2l[base + lane]      = __float2half_rn(w20 - __half2float(h0));
        g_w2l[base + lane + 32] = __float2half_rn(w21 - __half2float(h1));
        pa += w0; pb += w1;
    }
    u.s.ps[warp][lane]      = pa;
    u.s.ps[warp][lane + 32] = pb;
    __syncthreads();
    if (tid < 64)
        g_wsp[(n * NPT + pt) * KK + tid] =
            u.s.ps[0][tid] + u.s.ps[1][tid] + u.s.ps[2][tid] + u.s.ps[3][tid];
}

// ---------------- kernel C: GEMM2 via fp16 mma (2-product) ------------------
// CTA: (c-tile 128, n, p-split). D[k=64][c=128] = sum_p w2[k][p] * x[c][p].
// A = w2 fp16 hi/lo (direct cp.async, pre-split), B = x single fp16.
__global__ __launch_bounds__(128, 4) void k_vlad_mma(const float* __restrict__ x) {
    __shared__ __align__(16) float stgX[2][128][20];      // fp32 x stage
    __shared__ __align__(16) __half xsF[128][24];         // B fp16 tiles [c][p]
    __shared__ __align__(16) __half wsH[2][16][72];       // A^T hi tiles [p][k]
    __shared__ __align__(16) __half wsL[2][16][72];

    int ct = blockIdx.x, n = blockIdx.y, sp = blockIdx.z;
    int c0 = ct * 128;
    int p0  = (sp == 0) ? 0 : 544 + (sp - 1) * 528;
    int nch = (sp == 0) ? 34 : 33;
    int tid = threadIdx.x;
    int lane = tid & 31, warp = tid >> 5;

    int lr = lane & 7, lg = lane >> 3;
    int bRow = warp * 32 + ((lg & 2) ? 8 : 0) + lr;
    int bCol = (lg & 1) ? 8 : 0;
    uint32_t bAF0 = s2u32(&xsF[bRow][bCol]), bAF1 = s2u32(&xsF[bRow + 16][bCol]);
    int aRow = ((lg & 2) ? 8 : 0) + lr;
    int aColB = (lg & 1) ? 8 : 0;
    uint32_t aAH[2][4], aAL[2][4];
#pragma unroll
    for (int bb = 0; bb < 2; bb++)
#pragma unroll
        for (int mt = 0; mt < 4; mt++) {
            aAH[bb][mt] = s2u32(&wsH[bb][aRow][mt * 16 + aColB]);
            aAL[bb][mt] = s2u32(&wsL[bb][aRow][mt * 16 + aColB]);
        }

    const float* xrow = x + ((size_t)(n * CC + c0 + tid)) * PP + p0;
    int wp = tid >> 3, wk = (tid & 7) * 8;
    size_t wbase = ((size_t)n * PP + p0 + wp) * KK + wk;

#define VISSUE(ci, b) do {                                                     \
        const float* _xp = xrow + (ci) * 16;                                   \
        cpa16(s2u32(&stgX[b][tid][0]),  _xp);                                  \
        cpa16(s2u32(&stgX[b][tid][4]),  _xp + 4);                              \
        cpa16(s2u32(&stgX[b][tid][8]),  _xp + 8);                              \
        cpa16(s2u32(&stgX[b][tid][12]), _xp + 12);                             \
        size_t _wo = wbase + (size_t)(ci) * 16 * KK;                           \
        cpa16(s2u32(&wsH[b][wp][wk]), g_w2h + _wo);                            \
        cpa16(s2u32(&wsL[b][wp][wk]), g_w2l + _wo);                            \
    } while (0)

    float d[4][4][4] = {};

    VISSUE(0, 0); CP_COMMIT();
    for (int i = 0; i < nch; i++) {
        int b = i & 1;
        if (i + 1 < nch) { VISSUE(i + 1, b ^ 1); CP_COMMIT(); CP_WAIT(1); }
        else CP_WAIT(0);
        // convert OWN staged x (16 values) to single fp16
        {
            uint32_t hp[8];
#pragma unroll
            for (int q = 0; q < 4; q++) {
                float4 v = *reinterpret_cast<float4*>(&stgX[b][tid][q * 4]);
                hp[q * 2]     = packh(v.x, v.y);
                hp[q * 2 + 1] = packh(v.z, v.w);
            }
            *reinterpret_cast<uint4*>(&xsF[tid][0]) = make_uint4(hp[0], hp[1], hp[2], hp[3]);
            *reinterpret_cast<uint4*>(&xsF[tid][8]) = make_uint4(hp[4], hp[5], hp[6], hp[7]);
        }
        __syncthreads();
        uint32_t bf[8];
        LDSM4(bf[0], bf[1], bf[2], bf[3], bAF0);
        LDSM4(bf[4], bf[5], bf[6], bf[7], bAF1);
#pragma unroll
        for (int mt = 0; mt < 4; mt++) {
            uint32_t ah[4], al[4];
            LDSM4T(ah[0], ah[1], ah[2], ah[3], aAH[b][mt]);
            LDSM4T(al[0], al[1], al[2], al[3], aAL[b][mt]);
#pragma unroll
            for (int ng = 0; ng < 4; ng++) {
                MMAH(d[mt][ng], ah, bf[ng * 2], bf[ng * 2 + 1]);
                MMAH(d[mt][ng], al, bf[ng * 2], bf[ng * 2 + 1]);
            }
        }
        __syncthreads();
    }
    int grp = lane >> 2, q = lane & 3;
#pragma unroll
    for (int mt = 0; mt < 4; mt++)
#pragma unroll
        for (int ng = 0; ng < 4; ng++) {
            int k = mt * 16 + grp;
            int c = c0 + warp * 32 + ng * 8 + q * 2;
            size_t o = (((size_t)sp * NN + n) * KK + k) * CC + c;
            *reinterpret_cast<float2*>(&g_vp[o]) =
                make_float2(d[mt][ng][0], d[mt][ng][1]);
            *reinterpret_cast<float2*>(&g_vp[o + 8 * CC]) =
                make_float2(d[mt][ng][2], d[mt][ng][3]);
        }
}

// ---------------- kernel E: reduce partials + residual + intra L2 ----------
__global__ __launch_bounds__(256) void k_norm1(const float* __restrict__ cent,
                                               float* __restrict__ out) {
    __shared__ float red[256];
    int k = blockIdx.x, n = blockIdx.y, tid = threadIdx.x;
    float wsum = 0.f;
#pragma unroll
    for (int t = 0; t < NPT; t++) wsum += g_wsp[(n * NPT + t) * KK + k];

    float t1a = 0.f, t1b = 0.f;
#pragma unroll
    for (int s = 0; s < NSPLIT; s++) {
        size_t b = (((size_t)s * NN + n) * KK + k) * CC;
        t1a += g_vp[b + tid];
        t1b += g_vp[b + tid + 256];
    }
    size_t base = (size_t)n * KC + (size_t)k * CC;
    float v1 = t1a - wsum * cent[k * CC + tid];
    float v2 = t1b - wsum * cent[k * CC + tid + 256];
    red[tid] = v1 * v1 + v2 * v2;
    __syncthreads();
    for (int o = 128; o > 0; o >>= 1) {
        if (tid < o) red[tid] += red[tid + o];
        __syncthreads();
    }
    float tot = red[0];
    float inv = 1.f / fmaxf(sqrtf(tot), 1e-12f);
    out[base + tid]       = v1 * inv;
    out[base + tid + 256] = v2 * inv;
    if (tid == 0) g_gpart[n * KK + k] = tot * inv * inv;
}

// ---------------- kernel F: global L2 normalize ------------------------------
__global__ __launch_bounds__(256) void k_norm2(float* __restrict__ out) {
    __shared__ float s[KK];
    __shared__ float ginv;
    size_t i = (size_t)blockIdx.x * 256 + threadIdx.x;
    int n = (int)(i >> 15);
    if (threadIdx.x < KK) s[threadIdx.x] = g_gpart[n * KK + threadIdx.x];
    __syncthreads();
    if (threadIdx.x == 0) {
        float t = 0.f;
#pragma unroll
        for (int j = 0; j < KK; j++) t += s[j];
        ginv = 1.f / fmaxf(sqrtf(t), 1e-12f);
    }
    __syncthreads();
    out[i] *= ginv;
}

// ---------------- launch -----------------------------------------------------
extern "C" void kernel_launch(void* const* d_in, const int* in_sizes, int n_in,
                              void* d_out, int out_size) {
    const float* x      = (const float*)d_in[0];
    const float* conv_w = (const float*)d_in[1];
    const float* attn_w = (const float*)d_in[2];
    const float* attn_b = (const float*)d_in[3];
    const float* cent   = (const float*)d_in[4];
    float* out = (float*)d_out;
    (void)in_sizes; (void)n_in; (void)out_size;

    k_transpose<<<(CC * KK + 255) / 256, 256>>>(conv_w);
    k_assign_mma<<<dim3(NPT, NN), 128>>>(x, attn_w, attn_b);
    k_vlad_mma<<<dim3(4, NN, NSPLIT), 128>>>(x);
    k_norm1<<<dim3(KK, NN), 256>>>(cent, out);
    k_norm2<<<(NN * KC) / 256, 256>>>(out);
}